// round 1
// baseline (speedup 1.0000x reference)
#include <cuda_runtime.h>
#include <cstdint>
#include <cstddef>

#define Bv   4
#define Sv   4096
#define Dv   256
#define Hv   4
#define DEP  64
#define DFFv 1024
#define MTOK (Bv*Sv)

// ---------------- scratch (device globals; no allocation in kernel_launch) ----
__device__ float g_Q [MTOK*Dv];
__device__ float g_K [MTOK*Dv];
__device__ float g_V [MTOK*Dv];
__device__ float g_ctx[MTOK*Dv];
__device__ float g_x1[MTOK*Dv];
__device__ float g_h [(size_t)MTOK*DFFv];

// ---------------- helpers ----------------------------------------------------
__device__ __forceinline__ float to_tf32(float x){
    uint32_t u; asm("cvt.rna.tf32.f32 %0, %1;" : "=r"(u) : "f"(x));
    return __uint_as_float(u);
}

__device__ __forceinline__ void mma_tf32(float* c, const uint32_t* a,
                                         uint32_t b0, uint32_t b1){
    asm volatile(
      "mma.sync.aligned.m16n8k8.row.col.f32.tf32.tf32.f32 "
      "{%0,%1,%2,%3},{%4,%5,%6,%7},{%8,%9},{%0,%1,%2,%3};\n"
      : "+f"(c[0]), "+f"(c[1]), "+f"(c[2]), "+f"(c[3])
      : "r"(a[0]), "r"(a[1]), "r"(a[2]), "r"(a[3]), "r"(b0), "r"(b1));
}

__device__ __forceinline__ float blockReduceSum(float v, float* red){
    int lane = threadIdx.x & 31, wid = threadIdx.x >> 5;
    #pragma unroll
    for (int o = 16; o; o >>= 1) v += __shfl_xor_sync(0xffffffffu, v, o);
    if (lane == 0) red[wid] = v;
    __syncthreads();
    if (wid == 0){
        float t = (lane < 8) ? red[lane] : 0.f;
        #pragma unroll
        for (int o = 4; o; o >>= 1) t += __shfl_xor_sync(0xffffffffu, t, o);
        if (lane == 0) red[0] = t;
    }
    __syncthreads();
    float r = red[0];
    __syncthreads();          // allow red[] reuse by the next reduction
    return r;
}

// ---------------- generic tf32 GEMM: Y = X@W + bias (+res) (relu) -------------
// BM=128 BN=64 BK=32, 8 warps in 4x2, warp tile 32x32 (2 m-tiles x 4 n-tiles)
template<bool RELU>
__global__ __launch_bounds__(256) void gemm_kernel(
    const float* __restrict__ X, const float* __restrict__ W,
    const float* __restrict__ bias, const float* __restrict__ res,
    float* __restrict__ Y, int M, int N, int K)
{
    __shared__ float As[128][36];   // row-major, pad 36 -> conflict-free frag reads
    __shared__ float Bs[64][36];    // B stored transposed [n][k]

    const int tid  = threadIdx.x;
    const int lane = tid & 31;
    const int gid  = lane >> 2, tig = lane & 3;
    const int wid  = tid >> 5;
    const int wm   = wid >> 1, wn = wid & 1;
    const int bm   = blockIdx.y * 128, bn = blockIdx.x * 64;

    float acc[2][4][4];
    #pragma unroll
    for (int i = 0; i < 2; i++)
        #pragma unroll
        for (int j = 0; j < 4; j++)
            #pragma unroll
            for (int k = 0; k < 4; k++) acc[i][j][k] = 0.f;

    const int ar  = tid >> 3;            // A row base (0..31)
    const int ac  = (tid & 7) * 4;       // A col
    const int br  = tid & 31;            // B k-row (lane -> conflict-free STS)
    const int bc0 = (tid >> 5) * 4;      // B n-col base

    for (int k0 = 0; k0 < K; k0 += 32){
        __syncthreads();
        #pragma unroll
        for (int it = 0; it < 4; it++){
            int r = ar + it * 32;
            float4 v = *reinterpret_cast<const float4*>(X + (size_t)(bm + r) * K + k0 + ac);
            As[r][ac+0] = to_tf32(v.x); As[r][ac+1] = to_tf32(v.y);
            As[r][ac+2] = to_tf32(v.z); As[r][ac+3] = to_tf32(v.w);
        }
        #pragma unroll
        for (int it = 0; it < 2; it++){
            int c = bc0 + it * 32;
            float4 v = *reinterpret_cast<const float4*>(W + (size_t)(k0 + br) * N + bn + c);
            Bs[c+0][br] = to_tf32(v.x); Bs[c+1][br] = to_tf32(v.y);
            Bs[c+2][br] = to_tf32(v.z); Bs[c+3][br] = to_tf32(v.w);
        }
        __syncthreads();

        #pragma unroll
        for (int kk = 0; kk < 32; kk += 8){
            uint32_t af[2][4], bf[4][2];
            #pragma unroll
            for (int mt = 0; mt < 2; mt++){
                int r0 = wm * 32 + mt * 16;
                af[mt][0] = __float_as_uint(As[r0+gid  ][kk+tig  ]);
                af[mt][1] = __float_as_uint(As[r0+gid+8][kk+tig  ]);
                af[mt][2] = __float_as_uint(As[r0+gid  ][kk+tig+4]);
                af[mt][3] = __float_as_uint(As[r0+gid+8][kk+tig+4]);
            }
            #pragma unroll
            for (int nt = 0; nt < 4; nt++){
                int c0 = wn * 32 + nt * 8;
                bf[nt][0] = __float_as_uint(Bs[c0+gid][kk+tig  ]);
                bf[nt][1] = __float_as_uint(Bs[c0+gid][kk+tig+4]);
            }
            #pragma unroll
            for (int mt = 0; mt < 2; mt++)
                #pragma unroll
                for (int nt = 0; nt < 4; nt++)
                    mma_tf32(acc[mt][nt], af[mt], bf[nt][0], bf[nt][1]);
        }
    }

    // epilogue: +bias (+res) (relu), float2 stores
    #pragma unroll
    for (int mt = 0; mt < 2; mt++){
        #pragma unroll
        for (int nt = 0; nt < 4; nt++){
            int col = bn + wn * 32 + nt * 8 + 2 * tig;
            float b0 = bias[col], b1 = bias[col+1];
            #pragma unroll
            for (int half = 0; half < 2; half++){
                int row = bm + wm * 32 + mt * 16 + gid + half * 8;
                float v0 = acc[mt][nt][half*2+0] + b0;
                float v1 = acc[mt][nt][half*2+1] + b1;
                if (res){
                    v0 += res[(size_t)row * N + col];
                    v1 += res[(size_t)row * N + col + 1];
                }
                if (RELU){ v0 = fmaxf(v0, 0.f); v1 = fmaxf(v1, 0.f); }
                *reinterpret_cast<float2*>(Y + (size_t)row * N + col) = make_float2(v0, v1);
            }
        }
    }
}

// ---------------- flash attention (tf32 mma, online softmax) ------------------
// CTA: 128 queries of one (b,h). 8 warps x 16 rows. Loop over 32 key tiles of 128.
#define ATTN_SMEM_FLOATS (128*68*2 + 64*132 + 128*132 + 128)

__global__ __launch_bounds__(256, 1) void attn_kernel(
    const float* __restrict__ Q, const float* __restrict__ K,
    const float* __restrict__ V, const float* __restrict__ mask,
    float* __restrict__ O)
{
    extern __shared__ float sm[];
    float* sQ    = sm;                  // [128][68]
    float* sK    = sQ  + 128*68;        // [128][68]
    float* sVT   = sK  + 128*68;        // [64][132]  V transposed (d, key)
    float* sP    = sVT + 64*132;        // [128][132]
    float* sMask = sP  + 128*132;       // [128]

    const int tid = threadIdx.x, lane = tid & 31, wid = tid >> 5;
    const int gid = lane >> 2, tig = lane & 3;
    const int m0  = wid * 16;
    const int bh  = blockIdx.y;
    const int b   = bh >> 2, h = bh & 3;
    const int q0  = blockIdx.x * 128;
    const float* Qb = Q + (size_t)b*Sv*Dv + (size_t)h*DEP;
    const float* Kb = K + (size_t)b*Sv*Dv + (size_t)h*DEP;
    const float* Vb = V + (size_t)b*Sv*Dv + (size_t)h*DEP;

    // stage Q tile (coalesced), tf32-rounded
    {
        int r = tid >> 4, c = (tid & 15) * 4;
        #pragma unroll
        for (int it = 0; it < 8; it++){
            float4 v = *reinterpret_cast<const float4*>(Qb + (size_t)(q0 + r + it*16)*Dv + c);
            float* d = sQ + (r + it*16)*68 + c;
            d[0]=to_tf32(v.x); d[1]=to_tf32(v.y); d[2]=to_tf32(v.z); d[3]=to_tf32(v.w);
        }
    }
    __syncthreads();

    // Q fragments live in registers for the whole kernel (8 k-steps over d=64)
    uint32_t qf[8][4];
    #pragma unroll
    for (int kd = 0; kd < 8; kd++){
        int c = kd * 8;
        qf[kd][0] = __float_as_uint(sQ[(m0+gid  )*68 + c+tig  ]);
        qf[kd][1] = __float_as_uint(sQ[(m0+gid+8)*68 + c+tig  ]);
        qf[kd][2] = __float_as_uint(sQ[(m0+gid  )*68 + c+tig+4]);
        qf[kd][3] = __float_as_uint(sQ[(m0+gid+8)*68 + c+tig+4]);
    }

    float o[8][4];
    #pragma unroll
    for (int i = 0; i < 8; i++){ o[i][0]=o[i][1]=o[i][2]=o[i][3]=0.f; }
    float mrow[2] = {-1e30f, -1e30f};
    float lrow[2] = {0.f, 0.f};

    for (int kt = 0; kt < Sv/128; kt++){
        const int kbase = kt * 128;
        __syncthreads();                      // prior tile fully consumed
        // K tile (coalesced)
        {
            int r = tid >> 4, c = (tid & 15) * 4;
            #pragma unroll
            for (int it = 0; it < 8; it++){
                float4 v = *reinterpret_cast<const float4*>(Kb + (size_t)(kbase + r + it*16)*Dv + c);
                float* d = sK + (r + it*16)*68 + c;
                d[0]=to_tf32(v.x); d[1]=to_tf32(v.y); d[2]=to_tf32(v.z); d[3]=to_tf32(v.w);
            }
        }
        // V tile transposed into sVT[d][key]; key=lane -> conflict-free STS
        {
            int d0 = wid * 4;
            #pragma unroll
            for (int kb2 = 0; kb2 < 4; kb2++){
                #pragma unroll
                for (int db = 0; db < 2; db++){
                    int kkey = lane + kb2 * 32;
                    int dd   = d0 + db * 32;
                    float4 v = *reinterpret_cast<const float4*>(Vb + (size_t)(kbase + kkey)*Dv + dd);
                    sVT[(dd+0)*132 + kkey] = to_tf32(v.x);
                    sVT[(dd+1)*132 + kkey] = to_tf32(v.y);
                    sVT[(dd+2)*132 + kkey] = to_tf32(v.z);
                    sVT[(dd+3)*132 + kkey] = to_tf32(v.w);
                }
            }
        }
        if (tid < 128) sMask[tid] = mask[(size_t)b*Sv + kbase + tid];
        __syncthreads();

        // ---- S = Q @ K^T : 16 n-tiles of 8 keys, 8 k-steps over d ----
        float p[16][4];
        #pragma unroll
        for (int nt = 0; nt < 16; nt++){ p[nt][0]=p[nt][1]=p[nt][2]=p[nt][3]=0.f; }
        #pragma unroll
        for (int kd = 0; kd < 8; kd++){
            int c = kd * 8;
            #pragma unroll
            for (int nt = 0; nt < 16; nt++){
                uint32_t b0 = __float_as_uint(sK[(nt*8+gid)*68 + c+tig  ]);
                uint32_t b1 = __float_as_uint(sK[(nt*8+gid)*68 + c+tig+4]);
                mma_tf32(p[nt], qf[kd], b0, b1);
            }
        }

        // ---- online softmax ----
        float rmax[2] = {-1e30f, -1e30f};
        #pragma unroll
        for (int nt = 0; nt < 16; nt++){
            #pragma unroll
            for (int j = 0; j < 4; j++){
                int col = nt*8 + 2*tig + (j & 1);
                float s = p[nt][j] * 0.125f - 1e9f * sMask[col];
                p[nt][j] = s;
                rmax[j>>1] = fmaxf(rmax[j>>1], s);
            }
        }
        #pragma unroll
        for (int hh = 0; hh < 2; hh++){
            rmax[hh] = fmaxf(rmax[hh], __shfl_xor_sync(0xffffffffu, rmax[hh], 1));
            rmax[hh] = fmaxf(rmax[hh], __shfl_xor_sync(0xffffffffu, rmax[hh], 2));
        }
        float mnew[2], alpha[2], rsum[2];
        #pragma unroll
        for (int hh = 0; hh < 2; hh++){
            mnew[hh]  = fmaxf(mrow[hh], rmax[hh]);
            alpha[hh] = __expf(mrow[hh] - mnew[hh]);
            rsum[hh]  = 0.f;
        }
        #pragma unroll
        for (int nt = 0; nt < 16; nt++){
            #pragma unroll
            for (int j = 0; j < 4; j++){
                float e = __expf(p[nt][j] - mnew[j>>1]);
                rsum[j>>1] += e;
                sP[(m0 + gid + (j>>1)*8)*132 + nt*8 + 2*tig + (j & 1)] = to_tf32(e);
            }
        }
        #pragma unroll
        for (int hh = 0; hh < 2; hh++){
            rsum[hh] += __shfl_xor_sync(0xffffffffu, rsum[hh], 1);
            rsum[hh] += __shfl_xor_sync(0xffffffffu, rsum[hh], 2);
            lrow[hh] = lrow[hh] * alpha[hh] + rsum[hh];
            mrow[hh] = mnew[hh];
        }
        #pragma unroll
        for (int nt = 0; nt < 8; nt++){
            o[nt][0] *= alpha[0]; o[nt][1] *= alpha[0];
            o[nt][2] *= alpha[1]; o[nt][3] *= alpha[1];
        }
        __syncwarp();   // P rows are warp-private: warp-level STS->LDS ordering

        // ---- O += P @ V : 16 k-steps over keys, 8 n-tiles over d ----
        #pragma unroll
        for (int ks = 0; ks < 16; ks++){
            int c = ks * 8;
            uint32_t af[4];
            af[0] = __float_as_uint(sP[(m0+gid  )*132 + c+tig  ]);
            af[1] = __float_as_uint(sP[(m0+gid+8)*132 + c+tig  ]);
            af[2] = __float_as_uint(sP[(m0+gid  )*132 + c+tig+4]);
            af[3] = __float_as_uint(sP[(m0+gid+8)*132 + c+tig+4]);
            #pragma unroll
            for (int nt = 0; nt < 8; nt++){
                uint32_t b0 = __float_as_uint(sVT[(nt*8+gid)*132 + c+tig  ]);
                uint32_t b1 = __float_as_uint(sVT[(nt*8+gid)*132 + c+tig+4]);
                mma_tf32(o[nt], af, b0, b1);
            }
        }
    }

    // normalize and write ctx[b][q][h*64+d]  (== transpose+reshape of reference)
    float inv0 = 1.f / lrow[0], inv1 = 1.f / lrow[1];
    #pragma unroll
    for (int nt = 0; nt < 8; nt++){
        int col  = h * DEP + nt * 8 + 2 * tig;
        int row0 = q0 + m0 + gid;
        *reinterpret_cast<float2*>(O + (size_t)(b*Sv + row0    )*Dv + col) =
            make_float2(o[nt][0]*inv0, o[nt][1]*inv0);
        *reinterpret_cast<float2*>(O + (size_t)(b*Sv + row0 + 8)*Dv + col) =
            make_float2(o[nt][2]*inv1, o[nt][3]*inv1);
    }
}

// ---------------- LayerNorm: one block per row, in-place capable --------------
__global__ __launch_bounds__(256) void ln_kernel(
    const float* __restrict__ in, float* __restrict__ out,
    const float* __restrict__ g, const float* __restrict__ bt,
    int N, float eps)
{
    __shared__ float red[8];
    const int row = blockIdx.x;
    const float* x = in + (size_t)row * N;
    const int vpt = N >> 8;      // 1 (N=256) or 4 (N=1024)
    float v[4];
    float s = 0.f;
    for (int i = 0; i < vpt; i++){ v[i] = x[threadIdx.x + (i << 8)]; s += v[i]; }
    s = blockReduceSum(s, red);
    float mu = s / N;
    float var = 0.f;
    for (int i = 0; i < vpt; i++){ float d = v[i] - mu; var += d * d; }
    var = blockReduceSum(var, red);
    float rstd = rsqrtf(var / N + eps);
    float* y = out + (size_t)row * N;
    for (int i = 0; i < vpt; i++){
        int c = threadIdx.x + (i << 8);
        y[c] = (v[i] - mu) * rstd * g[c] + bt[c];
    }
}

// ---------------- launch ------------------------------------------------------
extern "C" void kernel_launch(void* const* d_in, const int* in_sizes, int n_in,
                              void* d_out, int out_size)
{
    (void)in_sizes; (void)n_in; (void)out_size;
    const float* x    = (const float*)d_in[0];
    const float* mask = (const float*)d_in[1];
    const float* wq   = (const float*)d_in[2];
    const float* bq   = (const float*)d_in[3];
    const float* wk   = (const float*)d_in[4];
    const float* bk   = (const float*)d_in[5];
    const float* wv   = (const float*)d_in[6];
    const float* bv   = (const float*)d_in[7];
    const float* wo   = (const float*)d_in[8];
    const float* bo   = (const float*)d_in[9];
    const float* w1   = (const float*)d_in[10];
    const float* b1   = (const float*)d_in[11];
    const float* lnffg= (const float*)d_in[12];
    const float* lnffb= (const float*)d_in[13];
    const float* w2   = (const float*)d_in[14];
    const float* b2   = (const float*)d_in[15];
    const float* ln1g = (const float*)d_in[16];
    const float* ln1b = (const float*)d_in[17];
    const float* ln2g = (const float*)d_in[18];
    const float* ln2b = (const float*)d_in[19];
    float* out = (float*)d_out;

    float *Q, *K, *V, *CTX, *X1, *Hb;
    cudaGetSymbolAddress((void**)&Q,   g_Q);
    cudaGetSymbolAddress((void**)&K,   g_K);
    cudaGetSymbolAddress((void**)&V,   g_V);
    cudaGetSymbolAddress((void**)&CTX, g_ctx);
    cudaGetSymbolAddress((void**)&X1,  g_x1);
    cudaGetSymbolAddress((void**)&Hb,  g_h);

    const size_t attnSmem = (size_t)ATTN_SMEM_FLOATS * sizeof(float);
    cudaFuncSetAttribute(attn_kernel, cudaFuncAttributeMaxDynamicSharedMemorySize,
                         (int)attnSmem);

    const dim3 blk(256);
    const dim3 gP(Dv/64,   MTOK/128);   // N=256 GEMMs
    const dim3 gF(DFFv/64, MTOK/128);   // N=1024 GEMM

    // QKV projections
    gemm_kernel<false><<<gP, blk>>>(x, wq, bq, nullptr, Q, MTOK, Dv, Dv);
    gemm_kernel<false><<<gP, blk>>>(x, wk, bk, nullptr, K, MTOK, Dv, Dv);
    gemm_kernel<false><<<gP, blk>>>(x, wv, bv, nullptr, V, MTOK, Dv, Dv);

    // attention
    attn_kernel<<<dim3(Sv/128, Bv*Hv), blk, attnSmem>>>(Q, K, V, mask, CTX);

    // out-proj + residual, then LN1 (eps 1e-3)
    gemm_kernel<false><<<gP, blk>>>(CTX, wo, bo, x, X1, MTOK, Dv, Dv);
    ln_kernel<<<MTOK, blk>>>(X1, X1, ln1g, ln1b, Dv, 1e-3f);

    // FFN1 + relu, LN_ff (eps 1e-6)
    gemm_kernel<true><<<gF, blk>>>(X1, w1, b1, nullptr, Hb, MTOK, DFFv, Dv);
    ln_kernel<<<MTOK, blk>>>(Hb, Hb, lnffg, lnffb, DFFv, 1e-6f);

    // FFN2 + residual into d_out, LN2 (eps 1e-3)
    gemm_kernel<false><<<gP, blk>>>(Hb, w2, b2, X1, out, MTOK, Dv, DFFv);
    ln_kernel<<<MTOK, blk>>>(out, out, ln2g, ln2b, Dv, 1e-3f);
}

// round 3
// speedup vs baseline: 1.7184x; 1.7184x over previous
#include <cuda_runtime.h>
#include <cuda_fp16.h>
#include <cstdint>
#include <cstddef>

#define Bv   4
#define Sv   4096
#define Dv   256
#define Hv   4
#define DEP  64
#define DFFv 1024
#define MTOK (Bv*Sv)

// ---------------- scratch (device globals; no allocation in kernel_launch) ----
__device__ float  g_X1[MTOK*Dv];                 // out1 fp32 (residual)
__device__ float  g_H [(size_t)MTOK*DFFv];       // ffn intermediate fp32
__device__ __half g_xh  [MTOK*Dv];
__device__ __half g_Qh  [MTOK*Dv];
__device__ __half g_Kh  [MTOK*Dv];
__device__ __half g_Vh  [MTOK*Dv];
__device__ __half g_ctxh[MTOK*Dv];
__device__ __half g_x1h [MTOK*Dv];
__device__ __half g_hh  [(size_t)MTOK*DFFv];
// weights transposed to [n][k], fp16
__device__ __half g_wqT[Dv*Dv];
__device__ __half g_wkT[Dv*Dv];
__device__ __half g_wvT[Dv*Dv];
__device__ __half g_woT[Dv*Dv];
__device__ __half g_w1T[(size_t)DFFv*Dv];
__device__ __half g_w2T[(size_t)Dv*DFFv];

// ---------------- helpers ----------------------------------------------------
__device__ __forceinline__ void mma_f16(float* c, const uint32_t* a,
                                        uint32_t b0, uint32_t b1){
    asm volatile(
      "mma.sync.aligned.m16n8k16.row.col.f32.f16.f16.f32 "
      "{%0,%1,%2,%3},{%4,%5,%6,%7},{%8,%9},{%0,%1,%2,%3};\n"
      : "+f"(c[0]), "+f"(c[1]), "+f"(c[2]), "+f"(c[3])
      : "r"(a[0]), "r"(a[1]), "r"(a[2]), "r"(a[3]), "r"(b0), "r"(b1));
}
__device__ __forceinline__ uint32_t pack2(float a, float b){
    __half2 h = __floats2half2_rn(a, b);          // low = a, high = b
    return *reinterpret_cast<uint32_t*>(&h);
}
__device__ __forceinline__ uint32_t lds32(const __half* p){
    return *reinterpret_cast<const uint32_t*>(p);
}
__device__ __forceinline__ float blockReduceSum(float v, float* red){
    int lane = threadIdx.x & 31, wid = threadIdx.x >> 5;
    #pragma unroll
    for (int o = 16; o; o >>= 1) v += __shfl_xor_sync(0xffffffffu, v, o);
    if (lane == 0) red[wid] = v;
    __syncthreads();
    if (wid == 0){
        float t = (lane < 8) ? red[lane] : 0.f;
        #pragma unroll
        for (int o = 4; o; o >>= 1) t += __shfl_xor_sync(0xffffffffu, t, o);
        if (lane == 0) red[0] = t;
    }
    __syncthreads();
    float r = red[0];
    __syncthreads();
    return r;
}

// ---------------- fp32 -> fp16 convert ---------------------------------------
__global__ __launch_bounds__(256) void cvt_kernel(
    const float* __restrict__ in, __half* __restrict__ out, int n4)
{
    int i = blockIdx.x * blockDim.x + threadIdx.x;
    if (i < n4){
        float4 v = reinterpret_cast<const float4*>(in)[i];
        uint2 u;
        u.x = pack2(v.x, v.y);
        u.y = pack2(v.z, v.w);
        reinterpret_cast<uint2*>(out)[i] = u;
    }
}

// ---------------- fp32 [R][C] -> fp16 transposed [C][R] ----------------------
__global__ __launch_bounds__(256) void transp_kernel(
    const float* __restrict__ in, __half* __restrict__ out, int R, int C)
{
    __shared__ float t[32][33];
    int bx = blockIdx.x * 32, by = blockIdx.y * 32;
    int tx = threadIdx.x, ty = threadIdx.y;       // block (32,8)
    #pragma unroll
    for (int j = 0; j < 32; j += 8)
        t[ty + j][tx] = in[(size_t)(by + ty + j) * C + bx + tx];
    __syncthreads();
    #pragma unroll
    for (int j = 0; j < 32; j += 8)
        out[(size_t)(bx + ty + j) * R + by + tx] = __float2half_rn(t[tx][ty + j]);
}

// ---------------- fp16 GEMM: Y = A @ W + bias (+res) (relu) ------------------
// BM=128 BN=64 BK=32, 8 warps (4m x 2n), warp tile 32x32, mma m16n8k16.
// W supplied TRANSPOSED: Bt[n][k]. All fragment loads are contiguous LDS.32.
template<bool RELU, bool HOUT>
__global__ __launch_bounds__(256) void gemm_h(
    const __half* __restrict__ A, const __half* __restrict__ Bt,
    const float* __restrict__ bias, const float* __restrict__ res,
    float* __restrict__ Yf, __half* __restrict__ Yh, int M, int N, int K)
{
    __shared__ __half As[128*40];   // [m][k], stride 40 halves (80B)
    __shared__ __half Bs[64*40];    // [n][k], stride 40 halves

    const int tid  = threadIdx.x;
    const int lane = tid & 31;
    const int gid  = lane >> 2, tig = lane & 3;
    const int wid  = tid >> 5;
    const int wm   = wid >> 1, wn = wid & 1;
    const int bm   = blockIdx.y * 128, bn = blockIdx.x * 64;

    float acc[2][4][4];
    #pragma unroll
    for (int i = 0; i < 2; i++)
        #pragma unroll
        for (int j = 0; j < 4; j++)
            #pragma unroll
            for (int k = 0; k < 4; k++) acc[i][j][k] = 0.f;

    const int ar = tid >> 2;            // A row 0..63 (+64)
    const int ac = (tid & 3) * 8;       // A col chunk
    const int bn_ = tid >> 2;           // B n row 0..63
    const int bc  = (tid & 3) * 8;      // B k chunk

    for (int k0 = 0; k0 < K; k0 += 32){
        __syncthreads();
        #pragma unroll
        for (int ir = 0; ir < 2; ir++){
            int r = ar + ir * 64;
            uint4 v = *reinterpret_cast<const uint4*>(A + (size_t)(bm + r) * K + k0 + ac);
            *reinterpret_cast<uint4*>(&As[r * 40 + ac]) = v;
        }
        {
            uint4 v = *reinterpret_cast<const uint4*>(Bt + (size_t)(bn + bn_) * K + k0 + bc);
            *reinterpret_cast<uint4*>(&Bs[bn_ * 40 + bc]) = v;
        }
        __syncthreads();

        #pragma unroll
        for (int ks = 0; ks < 2; ks++){
            const int kc = ks * 16 + 2 * tig;
            uint32_t af[2][4];
            #pragma unroll
            for (int mt = 0; mt < 2; mt++){
                const __half* base = &As[(wm*32 + mt*16 + gid) * 40 + kc];
                af[mt][0] = lds32(base);               // row g,   k lo
                af[mt][1] = lds32(base + 8*40);        // row g+8, k lo
                af[mt][2] = lds32(base + 8);           // row g,   k hi
                af[mt][3] = lds32(base + 8*40 + 8);    // row g+8, k hi
            }
            #pragma unroll
            for (int nt = 0; nt < 4; nt++){
                const __half* nb = &Bs[(wn*32 + nt*8 + gid) * 40 + kc];
                uint32_t b0 = lds32(nb);               // k lo
                uint32_t b1 = lds32(nb + 8);           // k hi
                #pragma unroll
                for (int mt = 0; mt < 2; mt++)
                    mma_f16(acc[mt][nt], af[mt], b0, b1);
            }
        }
    }

    #pragma unroll
    for (int mt = 0; mt < 2; mt++){
        #pragma unroll
        for (int nt = 0; nt < 4; nt++){
            int col = bn + wn * 32 + nt * 8 + 2 * tig;
            float b0 = bias[col], b1 = bias[col + 1];
            int r0 = bm + wm * 32 + mt * 16 + gid;
            #pragma unroll
            for (int hf = 0; hf < 2; hf++){
                int row = r0 + hf * 8;
                float v0 = acc[mt][nt][hf*2+0] + b0;
                float v1 = acc[mt][nt][hf*2+1] + b1;
                if (res){
                    v0 += res[(size_t)row * N + col];
                    v1 += res[(size_t)row * N + col + 1];
                }
                if (RELU){ v0 = fmaxf(v0, 0.f); v1 = fmaxf(v1, 0.f); }
                if (HOUT){
                    __half2 hv = __floats2half2_rn(v0, v1);
                    *reinterpret_cast<__half2*>(Yh + (size_t)row * N + col) = hv;
                } else {
                    *reinterpret_cast<float2*>(Yf + (size_t)row * N + col) = make_float2(v0, v1);
                }
            }
        }
    }
}

// ---------------- flash attention fp16, register-resident P, no ldmatrix -----
// CTA: 128 queries of one (b,h); 8 warps x 16 rows. 128-key tiles processed as
// two 64-key halves. sK[key][d]; sVT[d][key] transposed.
#define SQ_STRIDE 72
#define SVT_STRIDE 136
#define ATTN_SMEM_BYTES (128*SQ_STRIDE*2 + 128*SQ_STRIDE*2 + 64*SVT_STRIDE*2 + 128*4)

__global__ __launch_bounds__(256, 2) void attn_h(
    const __half* __restrict__ Q, const __half* __restrict__ K,
    const __half* __restrict__ V, const float* __restrict__ mask,
    __half* __restrict__ O)
{
    extern __shared__ char smem_raw[];
    __half* sQ  = reinterpret_cast<__half*>(smem_raw);
    __half* sK  = sQ + 128*SQ_STRIDE;
    __half* sVT = sK + 128*SQ_STRIDE;
    float* sMask = reinterpret_cast<float*>(sVT + 64*SVT_STRIDE);

    const int tid = threadIdx.x, lane = tid & 31, wid = tid >> 5;
    const int gid = lane >> 2, tig = lane & 3;
    const int m0  = wid * 16;
    const int b   = blockIdx.y >> 2, h = blockIdx.y & 3;
    const int q0  = blockIdx.x * 128;
    const __half* Qb = Q + (size_t)b*Sv*Dv + (size_t)h*DEP;
    const __half* Kb = K + (size_t)b*Sv*Dv + (size_t)h*DEP;
    const __half* Vb = V + (size_t)b*Sv*Dv + (size_t)h*DEP;

    // stage Q tile [128][64] (coalesced uint4)
    {
        int r = tid >> 2, c0 = (tid & 3) * 16;
        #pragma unroll
        for (int ir = 0; ir < 2; ir++){
            int row = r + ir * 64;
            const __half* src = Qb + (size_t)(q0 + row) * Dv + c0;
            *reinterpret_cast<uint4*>(&sQ[row*SQ_STRIDE + c0    ]) =
                *reinterpret_cast<const uint4*>(src);
            *reinterpret_cast<uint4*>(&sQ[row*SQ_STRIDE + c0 + 8]) =
                *reinterpret_cast<const uint4*>(src + 8);
        }
    }
    __syncthreads();

    // Q fragments cached in registers for the whole kernel (4 k16 steps)
    uint32_t qf[4][4];
    #pragma unroll
    for (int kd = 0; kd < 4; kd++){
        const __half* base = &sQ[(m0 + gid)*SQ_STRIDE + kd*16 + 2*tig];
        qf[kd][0] = lds32(base);
        qf[kd][1] = lds32(base + 8*SQ_STRIDE);
        qf[kd][2] = lds32(base + 8);
        qf[kd][3] = lds32(base + 8*SQ_STRIDE + 8);
    }

    float o[8][4];
    #pragma unroll
    for (int i = 0; i < 8; i++){ o[i][0]=o[i][1]=o[i][2]=o[i][3]=0.f; }
    float mrow[2] = {-1e30f, -1e30f};
    float lrow[2] = {0.f, 0.f};

    for (int kt = 0; kt < Sv/128; kt++){
        const int kbase = kt * 128;
        __syncthreads();                      // prior tile fully consumed
        // K tile [128][64] (coalesced)
        {
            int r = tid >> 2, c0 = (tid & 3) * 16;
            #pragma unroll
            for (int ir = 0; ir < 2; ir++){
                int row = r + ir * 64;
                const __half* src = Kb + (size_t)(kbase + row) * Dv + c0;
                *reinterpret_cast<uint4*>(&sK[row*SQ_STRIDE + c0    ]) =
                    *reinterpret_cast<const uint4*>(src);
                *reinterpret_cast<uint4*>(&sK[row*SQ_STRIDE + c0 + 8]) =
                    *reinterpret_cast<const uint4*>(src + 8);
            }
        }
        // V tile transposed: sVT[d][key]; half2 of (key 2kp, 2kp+1) -> STS.32
        {
            int kp = tid & 63;                // key pair
            #pragma unroll
            for (int it = 0; it < 2; it++){
                int d0 = (tid >> 6) * 8 + it * 32;
                const __half* s0 = Vb + (size_t)(kbase + 2*kp    ) * Dv + d0;
                const __half* s1 = Vb + (size_t)(kbase + 2*kp + 1) * Dv + d0;
                uint4 va = *reinterpret_cast<const uint4*>(s0);
                uint4 vb = *reinterpret_cast<const uint4*>(s1);
                const __half* ha = reinterpret_cast<const __half*>(&va);
                const __half* hb = reinterpret_cast<const __half*>(&vb);
                #pragma unroll
                for (int j = 0; j < 8; j++){
                    __half2 pr = __halves2half2(ha[j], hb[j]);  // low = even key
                    *reinterpret_cast<uint32_t*>(&sVT[(d0+j)*SVT_STRIDE + 2*kp]) =
                        *reinterpret_cast<uint32_t*>(&pr);
                }
            }
        }
        if (tid < 128) sMask[tid] = mask[(size_t)b*Sv + kbase + tid];
        __syncthreads();

        #pragma unroll
        for (int hh2 = 0; hh2 < 2; hh2++){
            const int kh0 = hh2 * 64;
            // ---- S = Q @ K^T over 64 keys ----
            float p[8][4];
            #pragma unroll
            for (int nt = 0; nt < 8; nt++){ p[nt][0]=p[nt][1]=p[nt][2]=p[nt][3]=0.f; }
            #pragma unroll
            for (int kd = 0; kd < 4; kd++){
                #pragma unroll
                for (int nt = 0; nt < 8; nt++){
                    const __half* kbp = &sK[(kh0 + nt*8 + gid)*SQ_STRIDE + kd*16 + 2*tig];
                    uint32_t b0 = lds32(kbp);
                    uint32_t b1 = lds32(kbp + 8);
                    mma_f16(p[nt], qf[kd], b0, b1);
                }
            }
            // ---- online softmax ----
            float rmax[2] = {-1e30f, -1e30f};
            #pragma unroll
            for (int nt = 0; nt < 8; nt++){
                #pragma unroll
                for (int j = 0; j < 4; j++){
                    int key = kh0 + nt*8 + 2*tig + (j & 1);
                    float s = p[nt][j] * 0.125f - 1e9f * sMask[key];
                    p[nt][j] = s;
                    rmax[j>>1] = fmaxf(rmax[j>>1], s);
                }
            }
            #pragma unroll
            for (int hh = 0; hh < 2; hh++){
                rmax[hh] = fmaxf(rmax[hh], __shfl_xor_sync(0xffffffffu, rmax[hh], 1));
                rmax[hh] = fmaxf(rmax[hh], __shfl_xor_sync(0xffffffffu, rmax[hh], 2));
            }
            float mnew[2], alpha[2], rsum[2];
            #pragma unroll
            for (int hh = 0; hh < 2; hh++){
                mnew[hh]  = fmaxf(mrow[hh], rmax[hh]);
                alpha[hh] = __expf(mrow[hh] - mnew[hh]);
                rsum[hh]  = 0.f;
            }
            #pragma unroll
            for (int nt = 0; nt < 8; nt++){
                #pragma unroll
                for (int j = 0; j < 4; j++){
                    float e = __expf(p[nt][j] - mnew[j>>1]);
                    p[nt][j] = e;
                    rsum[j>>1] += e;
                }
            }
            #pragma unroll
            for (int hh = 0; hh < 2; hh++){
                rsum[hh] += __shfl_xor_sync(0xffffffffu, rsum[hh], 1);
                rsum[hh] += __shfl_xor_sync(0xffffffffu, rsum[hh], 2);
                lrow[hh] = lrow[hh] * alpha[hh] + rsum[hh];
                mrow[hh] = mnew[hh];
            }
            #pragma unroll
            for (int nt = 0; nt < 8; nt++){
                o[nt][0] *= alpha[0]; o[nt][1] *= alpha[0];
                o[nt][2] *= alpha[1]; o[nt][3] *= alpha[1];
            }
            // ---- O += P @ V (A packed from S accumulators) ----
            #pragma unroll
            for (int ks = 0; ks < 4; ks++){
                uint32_t ap[4];
                ap[0] = pack2(p[2*ks  ][0], p[2*ks  ][1]);   // row g,   k lo
                ap[1] = pack2(p[2*ks  ][2], p[2*ks  ][3]);   // row g+8, k lo
                ap[2] = pack2(p[2*ks+1][0], p[2*ks+1][1]);   // row g,   k hi
                ap[3] = pack2(p[2*ks+1][2], p[2*ks+1][3]);   // row g+8, k hi
                #pragma unroll
                for (int nt = 0; nt < 8; nt++){
                    const __half* vbp = &sVT[(nt*8 + gid)*SVT_STRIDE + kh0 + ks*16 + 2*tig];
                    uint32_t b0 = lds32(vbp);
                    uint32_t b1 = lds32(vbp + 8);
                    mma_f16(o[nt], ap, b0, b1);
                }
            }
        }
    }

    // normalize, write ctx fp16 at [b][q][h*64+d]
    float inv0 = 1.f / lrow[0], inv1 = 1.f / lrow[1];
    #pragma unroll
    for (int nt = 0; nt < 8; nt++){
        int col  = h * DEP + nt * 8 + 2 * tig;
        int row0 = q0 + m0 + gid;
        __half2 h0 = __floats2half2_rn(o[nt][0]*inv0, o[nt][1]*inv0);
        __half2 h1 = __floats2half2_rn(o[nt][2]*inv1, o[nt][3]*inv1);
        *reinterpret_cast<__half2*>(O + (size_t)(b*Sv + row0    )*Dv + col) = h0;
        *reinterpret_cast<__half2*>(O + (size_t)(b*Sv + row0 + 8)*Dv + col) = h1;
    }
}

// ---------------- LayerNorm: one block per row; f32 and/or f16 outputs --------
__global__ __launch_bounds__(256) void ln_kernel(
    const float* __restrict__ in, float* __restrict__ out, __half* __restrict__ outh,
    const float* __restrict__ g, const float* __restrict__ bt,
    int N, float eps)
{
    __shared__ float red[8];
    const int row = blockIdx.x;
    const float* x = in + (size_t)row * N;
    const int vpt = N >> 8;
    float v[4];
    float s = 0.f;
    for (int i = 0; i < vpt; i++){ v[i] = x[threadIdx.x + (i << 8)]; s += v[i]; }
    s = blockReduceSum(s, red);
    float mu = s / N;
    float var = 0.f;
    for (int i = 0; i < vpt; i++){ float d = v[i] - mu; var += d * d; }
    var = blockReduceSum(var, red);
    float rstd = rsqrtf(var / N + eps);
    for (int i = 0; i < vpt; i++){
        int c = threadIdx.x + (i << 8);
        float y = (v[i] - mu) * rstd * g[c] + bt[c];
        if (out)  out [(size_t)row * N + c] = y;
        if (outh) outh[(size_t)row * N + c] = __float2half_rn(y);
    }
}

// ---------------- launch ------------------------------------------------------
extern "C" void kernel_launch(void* const* d_in, const int* in_sizes, int n_in,
                              void* d_out, int out_size)
{
    (void)in_sizes; (void)n_in; (void)out_size;
    const float* x    = (const float*)d_in[0];
    const float* mask = (const float*)d_in[1];
    const float* wq   = (const float*)d_in[2];
    const float* bq   = (const float*)d_in[3];
    const float* wk   = (const float*)d_in[4];
    const float* bk   = (const float*)d_in[5];
    const float* wv   = (const float*)d_in[6];
    const float* bv   = (const float*)d_in[7];
    const float* wo   = (const float*)d_in[8];
    const float* bo   = (const float*)d_in[9];
    const float* w1   = (const float*)d_in[10];
    const float* b1   = (const float*)d_in[11];
    const float* lnffg= (const float*)d_in[12];
    const float* lnffb= (const float*)d_in[13];
    const float* w2   = (const float*)d_in[14];
    const float* b2   = (const float*)d_in[15];
    const float* ln1g = (const float*)d_in[16];
    const float* ln1b = (const float*)d_in[17];
    const float* ln2g = (const float*)d_in[18];
    const float* ln2b = (const float*)d_in[19];
    float* out = (float*)d_out;

    float  *X1, *Hb;
    __half *xh, *Qh, *Kh, *Vh, *ctxh, *x1h, *hh;
    __half *wqT, *wkT, *wvT, *woT, *w1T, *w2T;
    cudaGetSymbolAddress((void**)&X1,   g_X1);
    cudaGetSymbolAddress((void**)&Hb,   g_H);
    cudaGetSymbolAddress((void**)&xh,   g_xh);
    cudaGetSymbolAddress((void**)&Qh,   g_Qh);
    cudaGetSymbolAddress((void**)&Kh,   g_Kh);
    cudaGetSymbolAddress((void**)&Vh,   g_Vh);
    cudaGetSymbolAddress((void**)&ctxh, g_ctxh);
    cudaGetSymbolAddress((void**)&x1h,  g_x1h);
    cudaGetSymbolAddress((void**)&hh,   g_hh);
    cudaGetSymbolAddress((void**)&wqT,  g_wqT);
    cudaGetSymbolAddress((void**)&wkT,  g_wkT);
    cudaGetSymbolAddress((void**)&wvT,  g_wvT);
    cudaGetSymbolAddress((void**)&woT,  g_woT);
    cudaGetSymbolAddress((void**)&w1T,  g_w1T);
    cudaGetSymbolAddress((void**)&w2T,  g_w2T);

    cudaFuncSetAttribute(attn_h, cudaFuncAttributeMaxDynamicSharedMemorySize,
                         ATTN_SMEM_BYTES);

    const dim3 blk(256);
    const dim3 tb(32, 8);

    // x -> fp16; weights -> fp16 transposed [n][k]
    cvt_kernel<<<(MTOK*Dv/4 + 255)/256, blk>>>(x, xh, MTOK*Dv/4);
    transp_kernel<<<dim3(Dv/32,  Dv/32),   tb>>>(wq, wqT, Dv,   Dv);
    transp_kernel<<<dim3(Dv/32,  Dv/32),   tb>>>(wk, wkT, Dv,   Dv);
    transp_kernel<<<dim3(Dv/32,  Dv/32),   tb>>>(wv, wvT, Dv,   Dv);
    transp_kernel<<<dim3(Dv/32,  Dv/32),   tb>>>(wo, woT, Dv,   Dv);
    transp_kernel<<<dim3(DFFv/32, Dv/32),  tb>>>(w1, w1T, Dv,   DFFv);
    transp_kernel<<<dim3(Dv/32,  DFFv/32), tb>>>(w2, w2T, DFFv, Dv);

    const dim3 gP(Dv/64,   MTOK/128);   // N=256 GEMMs
    const dim3 gF(DFFv/64, MTOK/128);   // N=1024 GEMM

    // QKV projections (fp16 outputs)
    gemm_h<false,true><<<gP, blk>>>(xh, wqT, bq, nullptr, nullptr, Qh, MTOK, Dv, Dv);
    gemm_h<false,true><<<gP, blk>>>(xh, wkT, bk, nullptr, nullptr, Kh, MTOK, Dv, Dv);
    gemm_h<false,true><<<gP, blk>>>(xh, wvT, bv, nullptr, nullptr, Vh, MTOK, Dv, Dv);

    // attention
    attn_h<<<dim3(Sv/128, Bv*Hv), blk, ATTN_SMEM_BYTES>>>(Qh, Kh, Vh, mask, ctxh);

    // out-proj + residual (fp32), LN1 (eps 1e-3) -> X1 f32 + x1h f16
    gemm_h<false,false><<<gP, blk>>>(ctxh, woT, bo, x, X1, nullptr, MTOK, Dv, Dv);
    ln_kernel<<<MTOK, blk>>>(X1, X1, x1h, ln1g, ln1b, Dv, 1e-3f);

    // FFN1 + relu -> Hb f32, LN_ff (eps 1e-6) -> hh f16
    gemm_h<true,false><<<gF, blk>>>(x1h, w1T, b1, nullptr, Hb, nullptr, MTOK, DFFv, Dv);
    ln_kernel<<<MTOK, blk>>>(Hb, nullptr, hh, lnffg, lnffb, DFFv, 1e-6f);

    // FFN2 + residual into d_out, LN2 (eps 1e-3) in place
    gemm_h<false,false><<<gP, blk>>>(hh, w2T, b2, X1, out, nullptr, MTOK, Dv, DFFv);
    ln_kernel<<<MTOK, blk>>>(out, out, nullptr, ln2g, ln2b, Dv, 1e-3f);
}

// round 4
// speedup vs baseline: 2.0949x; 1.2191x over previous
#include <cuda_runtime.h>
#include <cuda_fp16.h>
#include <cstdint>
#include <cstddef>

#define Bv   4
#define Sv   4096
#define Dv   256
#define Hv   4
#define DEP  64
#define DFFv 1024
#define MTOK (Bv*Sv)

// ---------------- scratch (device globals) ------------------------------------
__device__ float  g_X1[MTOK*Dv];
__device__ float  g_H [(size_t)MTOK*DFFv];
__device__ __half g_xh  [MTOK*Dv];
__device__ __half g_Qh  [MTOK*Dv];
__device__ __half g_Kh  [MTOK*Dv];
__device__ __half g_Vh  [MTOK*Dv];
__device__ __half g_ctxh[MTOK*Dv];
__device__ __half g_x1h [MTOK*Dv];
__device__ __half g_hh  [(size_t)MTOK*DFFv];
__device__ __half g_wqT[Dv*Dv];
__device__ __half g_wkT[Dv*Dv];
__device__ __half g_wvT[Dv*Dv];
__device__ __half g_woT[Dv*Dv];
__device__ __half g_w1T[(size_t)DFFv*Dv];
__device__ __half g_w2T[(size_t)Dv*DFFv];

// ---------------- helpers ------------------------------------------------------
__device__ __forceinline__ uint32_t sm32(const void* p){
    return (uint32_t)__cvta_generic_to_shared(p);
}
__device__ __forceinline__ void cpa16(void* s, const void* g){
    asm volatile("cp.async.cg.shared.global [%0], [%1], 16;"
                 :: "r"(sm32(s)), "l"(g));
}
__device__ __forceinline__ void cpa_commit(){
    asm volatile("cp.async.commit_group;");
}
template<int N> __device__ __forceinline__ void cpa_wait(){
    asm volatile("cp.async.wait_group %0;" :: "n"(N));
}
__device__ __forceinline__ void mma_f16(float* c, const uint32_t* a,
                                        uint32_t b0, uint32_t b1){
    asm volatile(
      "mma.sync.aligned.m16n8k16.row.col.f32.f16.f16.f32 "
      "{%0,%1,%2,%3},{%4,%5,%6,%7},{%8,%9},{%0,%1,%2,%3};\n"
      : "+f"(c[0]), "+f"(c[1]), "+f"(c[2]), "+f"(c[3])
      : "r"(a[0]), "r"(a[1]), "r"(a[2]), "r"(a[3]), "r"(b0), "r"(b1));
}
__device__ __forceinline__ uint32_t pack2(float a, float b){
    __half2 h = __floats2half2_rn(a, b);
    return *reinterpret_cast<uint32_t*>(&h);
}
__device__ __forceinline__ uint32_t lds32(const __half* p){
    return *reinterpret_cast<const uint32_t*>(p);
}

// ---------------- prep: fp32 -> fp16 -------------------------------------------
__global__ __launch_bounds__(256) void cvt_kernel(
    const float* __restrict__ in, __half* __restrict__ out, int n4)
{
    int i = blockIdx.x * blockDim.x + threadIdx.x;
    if (i < n4){
        float4 v = reinterpret_cast<const float4*>(in)[i];
        uint2 u;
        u.x = pack2(v.x, v.y);
        u.y = pack2(v.z, v.w);
        reinterpret_cast<uint2*>(out)[i] = u;
    }
}

// ---------------- prep: transpose all 6 weights in one launch ------------------
__device__ __forceinline__ void transp_tile(
    const float* __restrict__ in, __half* __restrict__ out,
    int R, int C, int bx, int by)
{
    __shared__ float t[32][33];
    int tx = threadIdx.x, ty = threadIdx.y;         // block (32,8)
    #pragma unroll
    for (int j = 0; j < 32; j += 8)
        t[ty + j][tx] = in[(size_t)(by + ty + j) * C + bx + tx];
    __syncthreads();
    #pragma unroll
    for (int j = 0; j < 32; j += 8)
        out[(size_t)(bx + ty + j) * R + by + tx] = __float2half_rn(t[tx][ty + j]);
}

__global__ __launch_bounds__(256) void transp_all(
    const float* wq, const float* wk, const float* wv, const float* wo,
    const float* w1, const float* w2,
    __half* wqT, __half* wkT, __half* wvT, __half* woT,
    __half* w1T, __half* w2T)
{
    int bid = blockIdx.x;   // 0..767
    if (bid < 256){         // four 256x256 weights, 64 tiles each (8x8)
        int m = bid >> 6, t = bid & 63;
        int bx = (t & 7) * 32, by = (t >> 3) * 32;
        const float* in  = (m==0)? wq : (m==1)? wk : (m==2)? wv : wo;
        __half*      outp= (m==0)? wqT: (m==1)? wkT: (m==2)? wvT: woT;
        transp_tile(in, outp, Dv, Dv, bx, by);
    } else if (bid < 512){  // w1: [Dv][DFFv] -> [DFFv][Dv], tiles (32 x, 8 y)
        int t = bid - 256;
        int bx = (t & 31) * 32, by = (t >> 5) * 32;
        transp_tile(w1, w1T, Dv, DFFv, bx, by);
    } else {                // w2: [DFFv][Dv] -> [Dv][DFFv], tiles (8 x, 32 y)
        int t = bid - 512;
        int bx = (t & 7) * 32, by = (t >> 3) * 32;
        transp_tile(w2, w2T, DFFv, Dv, bx, by);
    }
}

// ---------------- fp16 GEMM, cp.async double-buffered --------------------------
// BM=128 BN=64 BK=32, 8 warps (4m x 2n), warp tile 32x32, mma m16n8k16.
// W pre-transposed: Bt[n][k].
template<bool RELU, bool HOUT>
__global__ __launch_bounds__(256) void gemm_h(
    const __half* __restrict__ A, const __half* __restrict__ Bt,
    const float* __restrict__ bias, const float* __restrict__ res,
    float* __restrict__ Yf, __half* __restrict__ Yh, int M, int N, int K)
{
    __shared__ __half As[2][128*40];
    __shared__ __half Bs[2][64*40];

    const int tid  = threadIdx.x;
    const int lane = tid & 31;
    const int gid  = lane >> 2, tig = lane & 3;
    const int wid  = tid >> 5;
    const int wm   = wid >> 1, wn = wid & 1;
    const int bm   = blockIdx.y * 128, bn = blockIdx.x * 64;

    float acc[2][4][4];
    #pragma unroll
    for (int i = 0; i < 2; i++)
        #pragma unroll
        for (int j = 0; j < 4; j++)
            #pragma unroll
            for (int k = 0; k < 4; k++) acc[i][j][k] = 0.f;

    const int ar  = tid >> 2;           // A row 0..63 (+64)
    const int ac  = (tid & 3) * 8;      // A col chunk (8 halves = 16B)
    const int bn_ = tid >> 2;           // B n row 0..63
    const int bc  = (tid & 3) * 8;      // B k chunk

    auto stage = [&](int k0, int st){
        #pragma unroll
        for (int ir = 0; ir < 2; ir++){
            int r = ar + ir * 64;
            cpa16(&As[st][r * 40 + ac], A + (size_t)(bm + r) * K + k0 + ac);
        }
        cpa16(&Bs[st][bn_ * 40 + bc], Bt + (size_t)(bn + bn_) * K + k0 + bc);
        cpa_commit();
    };

    stage(0, 0);
    int buf = 0;
    for (int k0 = 0; k0 < K; k0 += 32){
        bool nxt = (k0 + 32 < K);
        if (nxt) stage(k0 + 32, buf ^ 1);
        if (nxt) cpa_wait<1>(); else cpa_wait<0>();
        __syncthreads();

        const __half* Ab = As[buf];
        const __half* Bb = Bs[buf];
        #pragma unroll
        for (int ks = 0; ks < 2; ks++){
            const int kc = ks * 16 + 2 * tig;
            uint32_t af[2][4];
            #pragma unroll
            for (int mt = 0; mt < 2; mt++){
                const __half* base = &Ab[(wm*32 + mt*16 + gid) * 40 + kc];
                af[mt][0] = lds32(base);
                af[mt][1] = lds32(base + 8*40);
                af[mt][2] = lds32(base + 8);
                af[mt][3] = lds32(base + 8*40 + 8);
            }
            #pragma unroll
            for (int nt = 0; nt < 4; nt++){
                const __half* nb = &Bb[(wn*32 + nt*8 + gid) * 40 + kc];
                uint32_t b0 = lds32(nb);
                uint32_t b1 = lds32(nb + 8);
                #pragma unroll
                for (int mt = 0; mt < 2; mt++)
                    mma_f16(acc[mt][nt], af[mt], b0, b1);
            }
        }
        __syncthreads();
        buf ^= 1;
    }

    #pragma unroll
    for (int mt = 0; mt < 2; mt++){
        #pragma unroll
        for (int nt = 0; nt < 4; nt++){
            int col = bn + wn * 32 + nt * 8 + 2 * tig;
            float b0 = bias[col], b1 = bias[col + 1];
            int r0 = bm + wm * 32 + mt * 16 + gid;
            #pragma unroll
            for (int hf = 0; hf < 2; hf++){
                int row = r0 + hf * 8;
                float v0 = acc[mt][nt][hf*2+0] + b0;
                float v1 = acc[mt][nt][hf*2+1] + b1;
                if (res){
                    v0 += res[(size_t)row * N + col];
                    v1 += res[(size_t)row * N + col + 1];
                }
                if (RELU){ v0 = fmaxf(v0, 0.f); v1 = fmaxf(v1, 0.f); }
                if (HOUT){
                    __half2 hv = __floats2half2_rn(v0, v1);
                    *reinterpret_cast<__half2*>(Yh + (size_t)row * N + col) = hv;
                } else {
                    *reinterpret_cast<float2*>(Yf + (size_t)row * N + col) = make_float2(v0, v1);
                }
            }
        }
    }
}

// ---------------- flash attention, cp.async double-buffered --------------------
// CTA: 128 queries of one (b,h); 8 warps x 16 rows; 32 key-tiles of 128.
#define KST  72
#define VTST 136
#define NT_TILES (Sv/128)
// smem: sQ(128*72) + 2*sK(128*72) + 2*sVr(128*72) + sVT(64*136) + 2*mask(128 f32)
#define ATTN_SMEM_BYTES (128*KST*2*5 + 64*VTST*2 + 2*128*4)

__global__ __launch_bounds__(256, 2) void attn_h(
    const __half* __restrict__ Q, const __half* __restrict__ K,
    const __half* __restrict__ V, const float* __restrict__ mask,
    __half* __restrict__ O)
{
    extern __shared__ char smem_raw[];
    __half* sQ  = reinterpret_cast<__half*>(smem_raw);
    __half* sK0 = sQ  + 128*KST;
    __half* sK1 = sK0 + 128*KST;
    __half* sV0 = sK1 + 128*KST;
    __half* sV1 = sV0 + 128*KST;
    __half* sVT = sV1 + 128*KST;
    float* sMask0 = reinterpret_cast<float*>(sVT + 64*VTST);
    float* sMask1 = sMask0 + 128;

    const int tid = threadIdx.x, lane = tid & 31, wid = tid >> 5;
    const int gid = lane >> 2, tig = lane & 3;
    const int m0  = wid * 16;
    const int b   = blockIdx.y >> 2, h = blockIdx.y & 3;
    const int q0  = blockIdx.x * 128;
    const __half* Qb = Q + (size_t)b*Sv*Dv + (size_t)h*DEP;
    const __half* Kb = K + (size_t)b*Sv*Dv + (size_t)h*DEP;
    const __half* Vb = V + (size_t)b*Sv*Dv + (size_t)h*DEP;
    const float*  Mb = mask + (size_t)b*Sv;

    const int sr  = tid >> 2;            // staging row 0..63 (+64)
    const int sc  = (tid & 3) * 16;      // staging col (16 halves = 32B, two 16B)

    auto stageKVM = [&](int kt, __half* dK, __half* dV, float* dM){
        const int kbase = kt * 128;
        #pragma unroll
        for (int ir = 0; ir < 2; ir++){
            int row = sr + ir * 64;
            const __half* ks_ = Kb + (size_t)(kbase + row) * Dv + sc;
            cpa16(&dK[row*KST + sc    ], ks_);
            cpa16(&dK[row*KST + sc + 8], ks_ + 8);
            const __half* vs_ = Vb + (size_t)(kbase + row) * Dv + sc;
            cpa16(&dV[row*KST + sc    ], vs_);
            cpa16(&dV[row*KST + sc + 8], vs_ + 8);
        }
        if (tid < 32) cpa16(&dM[tid*4], Mb + kbase + tid*4);
    };

    // prologue: Q + tile0 as group0
    {
        #pragma unroll
        for (int ir = 0; ir < 2; ir++){
            int row = sr + ir * 64;
            const __half* src = Qb + (size_t)(q0 + row) * Dv + sc;
            cpa16(&sQ[row*KST + sc    ], src);
            cpa16(&sQ[row*KST + sc + 8], src + 8);
        }
        stageKVM(0, sK0, sV0, sMask0);
        cpa_commit();
    }
    cpa_wait<0>();
    __syncthreads();

    // Q fragments cached in registers (4 k16 steps over d=64)
    uint32_t qf[4][4];
    #pragma unroll
    for (int kd = 0; kd < 4; kd++){
        const __half* base = &sQ[(m0 + gid)*KST + kd*16 + 2*tig];
        qf[kd][0] = lds32(base);
        qf[kd][1] = lds32(base + 8*KST);
        qf[kd][2] = lds32(base + 8);
        qf[kd][3] = lds32(base + 8*KST + 8);
    }

    float o[8][4];
    #pragma unroll
    for (int i = 0; i < 8; i++){ o[i][0]=o[i][1]=o[i][2]=o[i][3]=0.f; }
    float mrow[2] = {-1e30f, -1e30f};
    float lrow[2] = {0.f, 0.f};

    const int vkp = tid & 63;            // V-transpose key pair
    const int vdb = (tid >> 6) * 8;      // V-transpose d base

    for (int kt = 0; kt < NT_TILES; kt++){
        const int buf = kt & 1;
        __half* cK = buf ? sK1 : sK0;
        __half* cV = buf ? sV1 : sV0;
        float*  cM = buf ? sMask1 : sMask0;
        const bool nxt = (kt + 1 < NT_TILES);
        if (nxt){
            stageKVM(kt + 1, buf ? sK0 : sK1, buf ? sV0 : sV1,
                     buf ? sMask0 : sMask1);
            cpa_commit();
        }

        // transpose V: sVr[buf] -> sVT[d][key]
        #pragma unroll
        for (int it = 0; it < 2; it++){
            int d0 = vdb + it * 32;
            uint4 va = *reinterpret_cast<const uint4*>(&cV[(2*vkp    )*KST + d0]);
            uint4 vb = *reinterpret_cast<const uint4*>(&cV[(2*vkp + 1)*KST + d0]);
            const __half* ha = reinterpret_cast<const __half*>(&va);
            const __half* hb = reinterpret_cast<const __half*>(&vb);
            #pragma unroll
            for (int j = 0; j < 8; j++){
                __half2 pr = __halves2half2(ha[j], hb[j]);
                *reinterpret_cast<uint32_t*>(&sVT[(d0+j)*VTST + 2*vkp]) =
                    *reinterpret_cast<uint32_t*>(&pr);
            }
        }

        // ---- S = Q @ K^T over full 128 keys (two 64-key halves) ----
        float p[2][8][4];
        #pragma unroll
        for (int hh2 = 0; hh2 < 2; hh2++)
            #pragma unroll
            for (int nt = 0; nt < 8; nt++){
                p[hh2][nt][0]=p[hh2][nt][1]=p[hh2][nt][2]=p[hh2][nt][3]=0.f;
            }
        #pragma unroll
        for (int hh2 = 0; hh2 < 2; hh2++){
            const int kh0 = hh2 * 64;
            #pragma unroll
            for (int kd = 0; kd < 4; kd++){
                #pragma unroll
                for (int nt = 0; nt < 8; nt++){
                    const __half* kbp = &cK[(kh0 + nt*8 + gid)*KST + kd*16 + 2*tig];
                    uint32_t b0 = lds32(kbp);
                    uint32_t b1 = lds32(kbp + 8);
                    mma_f16(p[hh2][nt], qf[kd], b0, b1);
                }
            }
        }
        __syncthreads();      // sVT writes visible before PV reads

        // ---- softmax over 128 keys ----
        float rmax[2] = {-1e30f, -1e30f};
        #pragma unroll
        for (int hh2 = 0; hh2 < 2; hh2++){
            #pragma unroll
            for (int nt = 0; nt < 8; nt++){
                #pragma unroll
                for (int j = 0; j < 4; j++){
                    int key = hh2*64 + nt*8 + 2*tig + (j & 1);
                    float s = p[hh2][nt][j] * 0.125f - 1e9f * cM[key];
                    p[hh2][nt][j] = s;
                    rmax[j>>1] = fmaxf(rmax[j>>1], s);
                }
            }
        }
        #pragma unroll
        for (int hh = 0; hh < 2; hh++){
            rmax[hh] = fmaxf(rmax[hh], __shfl_xor_sync(0xffffffffu, rmax[hh], 1));
            rmax[hh] = fmaxf(rmax[hh], __shfl_xor_sync(0xffffffffu, rmax[hh], 2));
        }
        float mnew[2], alpha[2], rsum[2];
        #pragma unroll
        for (int hh = 0; hh < 2; hh++){
            mnew[hh]  = fmaxf(mrow[hh], rmax[hh]);
            alpha[hh] = __expf(mrow[hh] - mnew[hh]);
            rsum[hh]  = 0.f;
        }
        #pragma unroll
        for (int hh2 = 0; hh2 < 2; hh2++)
            #pragma unroll
            for (int nt = 0; nt < 8; nt++)
                #pragma unroll
                for (int j = 0; j < 4; j++){
                    float e = __expf(p[hh2][nt][j] - mnew[j>>1]);
                    p[hh2][nt][j] = e;
                    rsum[j>>1] += e;
                }
        #pragma unroll
        for (int hh = 0; hh < 2; hh++){
            rsum[hh] += __shfl_xor_sync(0xffffffffu, rsum[hh], 1);
            rsum[hh] += __shfl_xor_sync(0xffffffffu, rsum[hh], 2);
            lrow[hh] = lrow[hh] * alpha[hh] + rsum[hh];
            mrow[hh] = mnew[hh];
        }
        #pragma unroll
        for (int nt = 0; nt < 8; nt++){
            o[nt][0] *= alpha[0]; o[nt][1] *= alpha[0];
            o[nt][2] *= alpha[1]; o[nt][3] *= alpha[1];
        }

        // ---- O += P @ V over 128 keys ----
        #pragma unroll
        for (int hh2 = 0; hh2 < 2; hh2++){
            const int kh0 = hh2 * 64;
            #pragma unroll
            for (int ks = 0; ks < 4; ks++){
                uint32_t ap[4];
                ap[0] = pack2(p[hh2][2*ks  ][0], p[hh2][2*ks  ][1]);
                ap[1] = pack2(p[hh2][2*ks  ][2], p[hh2][2*ks  ][3]);
                ap[2] = pack2(p[hh2][2*ks+1][0], p[hh2][2*ks+1][1]);
                ap[3] = pack2(p[hh2][2*ks+1][2], p[hh2][2*ks+1][3]);
                #pragma unroll
                for (int nt = 0; nt < 8; nt++){
                    const __half* vbp = &sVT[(nt*8 + gid)*VTST + kh0 + ks*16 + 2*tig];
                    uint32_t b0 = lds32(vbp);
                    uint32_t b1 = lds32(vbp + 8);
                    mma_f16(o[nt], ap, b0, b1);
                }
            }
        }
        if (nxt) cpa_wait<0>();
        __syncthreads();      // all reads of this stage done; next tile visible
    }

    float inv0 = 1.f / lrow[0], inv1 = 1.f / lrow[1];
    #pragma unroll
    for (int nt = 0; nt < 8; nt++){
        int col  = h * DEP + nt * 8 + 2 * tig;
        int row0 = q0 + m0 + gid;
        __half2 h0 = __floats2half2_rn(o[nt][0]*inv0, o[nt][1]*inv0);
        __half2 h1 = __floats2half2_rn(o[nt][2]*inv1, o[nt][3]*inv1);
        *reinterpret_cast<__half2*>(O + (size_t)(b*Sv + row0    )*Dv + col) = h0;
        *reinterpret_cast<__half2*>(O + (size_t)(b*Sv + row0 + 8)*Dv + col) = h1;
    }
}

// ---------------- LayerNorm: warp per row, no block barriers -------------------
__global__ __launch_bounds__(256) void ln_kernel(
    const float* __restrict__ in, float* __restrict__ out, __half* __restrict__ outh,
    const float* __restrict__ g, const float* __restrict__ bt,
    int N, float eps)
{
    const int lane = threadIdx.x & 31;
    const int row  = blockIdx.x * 8 + (threadIdx.x >> 5);
    const int nch  = N >> 7;                 // float4-chunks of 128 per row: 2 or 8
    const float* x = in + (size_t)row * N;

    float4 v[8];
    float s = 0.f;
    for (int j = 0; j < nch; j++){
        v[j] = *reinterpret_cast<const float4*>(x + j*128 + lane*4);
        s += v[j].x + v[j].y + v[j].z + v[j].w;
    }
    #pragma unroll
    for (int o = 16; o; o >>= 1) s += __shfl_xor_sync(0xffffffffu, s, o);
    float mu = s / N;
    float var = 0.f;
    for (int j = 0; j < nch; j++){
        float dx = v[j].x-mu, dy = v[j].y-mu, dz = v[j].z-mu, dw = v[j].w-mu;
        var += dx*dx + dy*dy + dz*dz + dw*dw;
    }
    #pragma unroll
    for (int o = 16; o; o >>= 1) var += __shfl_xor_sync(0xffffffffu, var, o);
    float rstd = rsqrtf(var / N + eps);

    for (int j = 0; j < nch; j++){
        int c = j*128 + lane*4;
        float4 gg = *reinterpret_cast<const float4*>(g  + c);
        float4 bb = *reinterpret_cast<const float4*>(bt + c);
        float y0 = (v[j].x - mu) * rstd * gg.x + bb.x;
        float y1 = (v[j].y - mu) * rstd * gg.y + bb.y;
        float y2 = (v[j].z - mu) * rstd * gg.z + bb.z;
        float y3 = (v[j].w - mu) * rstd * gg.w + bb.w;
        if (out)
            *reinterpret_cast<float4*>(out + (size_t)row * N + c) =
                make_float4(y0, y1, y2, y3);
        if (outh){
            uint2 u;
            u.x = pack2(y0, y1);
            u.y = pack2(y2, y3);
            *reinterpret_cast<uint2*>(outh + (size_t)row * N + c) = u;
        }
    }
}

// ---------------- launch --------------------------------------------------------
extern "C" void kernel_launch(void* const* d_in, const int* in_sizes, int n_in,
                              void* d_out, int out_size)
{
    (void)in_sizes; (void)n_in; (void)out_size;
    const float* x    = (const float*)d_in[0];
    const float* mask = (const float*)d_in[1];
    const float* wq   = (const float*)d_in[2];
    const float* bq   = (const float*)d_in[3];
    const float* wk   = (const float*)d_in[4];
    const float* bk   = (const float*)d_in[5];
    const float* wv   = (const float*)d_in[6];
    const float* bv   = (const float*)d_in[7];
    const float* wo   = (const float*)d_in[8];
    const float* bo   = (const float*)d_in[9];
    const float* w1   = (const float*)d_in[10];
    const float* b1   = (const float*)d_in[11];
    const float* lnffg= (const float*)d_in[12];
    const float* lnffb= (const float*)d_in[13];
    const float* w2   = (const float*)d_in[14];
    const float* b2   = (const float*)d_in[15];
    const float* ln1g = (const float*)d_in[16];
    const float* ln1b = (const float*)d_in[17];
    const float* ln2g = (const float*)d_in[18];
    const float* ln2b = (const float*)d_in[19];
    float* out = (float*)d_out;

    float  *X1, *Hb;
    __half *xh, *Qh, *Kh, *Vh, *ctxh, *x1h, *hh;
    __half *wqT, *wkT, *wvT, *woT, *w1T, *w2T;
    cudaGetSymbolAddress((void**)&X1,   g_X1);
    cudaGetSymbolAddress((void**)&Hb,   g_H);
    cudaGetSymbolAddress((void**)&xh,   g_xh);
    cudaGetSymbolAddress((void**)&Qh,   g_Qh);
    cudaGetSymbolAddress((void**)&Kh,   g_Kh);
    cudaGetSymbolAddress((void**)&Vh,   g_Vh);
    cudaGetSymbolAddress((void**)&ctxh, g_ctxh);
    cudaGetSymbolAddress((void**)&x1h,  g_x1h);
    cudaGetSymbolAddress((void**)&hh,   g_hh);
    cudaGetSymbolAddress((void**)&wqT,  g_wqT);
    cudaGetSymbolAddress((void**)&wkT,  g_wkT);
    cudaGetSymbolAddress((void**)&wvT,  g_wvT);
    cudaGetSymbolAddress((void**)&woT,  g_woT);
    cudaGetSymbolAddress((void**)&w1T,  g_w1T);
    cudaGetSymbolAddress((void**)&w2T,  g_w2T);

    cudaFuncSetAttribute(attn_h, cudaFuncAttributeMaxDynamicSharedMemorySize,
                         ATTN_SMEM_BYTES);

    const dim3 blk(256);
    const dim3 gP(Dv/64,   MTOK/128);
    const dim3 gF(DFFv/64, MTOK/128);

    // launch 1: x -> fp16
    cvt_kernel<<<(MTOK*Dv/4 + 255)/256, blk>>>(x, xh, MTOK*Dv/4);
    // launch 2: all weight transposes
    transp_all<<<768, dim3(32,8)>>>(wq, wk, wv, wo, w1, w2,
                                    wqT, wkT, wvT, woT, w1T, w2T);
    // launches 3-5: QKV projections
    gemm_h<false,true><<<gP, blk>>>(xh, wqT, bq, nullptr, nullptr, Qh, MTOK, Dv, Dv);
    gemm_h<false,true><<<gP, blk>>>(xh, wkT, bk, nullptr, nullptr, Kh, MTOK, Dv, Dv);
    gemm_h<false,true><<<gP, blk>>>(xh, wvT, bv, nullptr, nullptr, Vh, MTOK, Dv, Dv);
    // launch 6: attention (profiled by ncu -s 5 -c 1)
    attn_h<<<dim3(Sv/128, Bv*Hv), blk, ATTN_SMEM_BYTES>>>(Qh, Kh, Vh, mask, ctxh);
    // out-proj + residual, LN1
    gemm_h<false,false><<<gP, blk>>>(ctxh, woT, bo, x, X1, nullptr, MTOK, Dv, Dv);
    ln_kernel<<<MTOK/8, blk>>>(X1, X1, x1h, ln1g, ln1b, Dv, 1e-3f);
    // FFN1 + relu, LN_ff
    gemm_h<true,false><<<gF, blk>>>(x1h, w1T, b1, nullptr, Hb, nullptr, MTOK, DFFv, Dv);
    ln_kernel<<<MTOK/8, blk>>>(Hb, nullptr, hh, lnffg, lnffb, DFFv, 1e-6f);
    // FFN2 + residual, LN2
    gemm_h<false,false><<<gP, blk>>>(hh, w2T, b2, X1, out, nullptr, MTOK, Dv, DFFv);
    ln_kernel<<<MTOK/8, blk>>>(out, out, nullptr, ln2g, ln2b, Dv, 1e-3f);
}

// round 5
// speedup vs baseline: 2.0985x; 1.0017x over previous
#include <cuda_runtime.h>
#include <cuda_fp16.h>
#include <cstdint>
#include <cstddef>

#define Bv   4
#define Sv   4096
#define Dv   256
#define Hv   4
#define DEP  64
#define DFFv 1024
#define MTOK (Bv*Sv)

// ---------------- scratch (device globals) ------------------------------------
__device__ float  g_X1[MTOK*Dv];
__device__ float  g_H [(size_t)MTOK*DFFv];
__device__ __half g_xh  [MTOK*Dv];
__device__ __half g_Qh  [MTOK*Dv];
__device__ __half g_Kh  [MTOK*Dv];
__device__ __half g_Vh  [MTOK*Dv];
__device__ __half g_ctxh[MTOK*Dv];
__device__ __half g_x1h [MTOK*Dv];
__device__ __half g_hh  [(size_t)MTOK*DFFv];
__device__ __half g_wqT[Dv*Dv];
__device__ __half g_wkT[Dv*Dv];
__device__ __half g_wvT[Dv*Dv];
__device__ __half g_woT[Dv*Dv];
__device__ __half g_w1T[(size_t)DFFv*Dv];
__device__ __half g_w2T[(size_t)Dv*DFFv];

// ---------------- helpers ------------------------------------------------------
__device__ __forceinline__ uint32_t sm32(const void* p){
    return (uint32_t)__cvta_generic_to_shared(p);
}
__device__ __forceinline__ void cpa16(void* s, const void* g){
    asm volatile("cp.async.cg.shared.global [%0], [%1], 16;"
                 :: "r"(sm32(s)), "l"(g));
}
__device__ __forceinline__ void cpa_commit(){
    asm volatile("cp.async.commit_group;");
}
template<int N> __device__ __forceinline__ void cpa_wait(){
    asm volatile("cp.async.wait_group %0;" :: "n"(N));
}
__device__ __forceinline__ void mma_f16(float* c, const uint32_t* a,
                                        uint32_t b0, uint32_t b1){
    asm volatile(
      "mma.sync.aligned.m16n8k16.row.col.f32.f16.f16.f32 "
      "{%0,%1,%2,%3},{%4,%5,%6,%7},{%8,%9},{%0,%1,%2,%3};\n"
      : "+f"(c[0]), "+f"(c[1]), "+f"(c[2]), "+f"(c[3])
      : "r"(a[0]), "r"(a[1]), "r"(a[2]), "r"(a[3]), "r"(b0), "r"(b1));
}
__device__ __forceinline__ uint32_t pack2(float a, float b){
    __half2 h = __floats2half2_rn(a, b);
    return *reinterpret_cast<uint32_t*>(&h);
}
__device__ __forceinline__ uint32_t lds32(const __half* p){
    return *reinterpret_cast<const uint32_t*>(p);
}

// ---------------- prep: fp32 -> fp16 -------------------------------------------
__global__ __launch_bounds__(256) void cvt_kernel(
    const float* __restrict__ in, __half* __restrict__ out, int n4)
{
    int i = blockIdx.x * blockDim.x + threadIdx.x;
    if (i < n4){
        float4 v = reinterpret_cast<const float4*>(in)[i];
        uint2 u;
        u.x = pack2(v.x, v.y);
        u.y = pack2(v.z, v.w);
        reinterpret_cast<uint2*>(out)[i] = u;
    }
}

// ---------------- prep: transpose all 6 weights in one launch ------------------
__device__ __forceinline__ void transp_tile(
    const float* __restrict__ in, __half* __restrict__ out,
    int R, int C, int bx, int by)
{
    __shared__ float t[32][33];
    int tx = threadIdx.x, ty = threadIdx.y;         // block (32,8)
    #pragma unroll
    for (int j = 0; j < 32; j += 8)
        t[ty + j][tx] = in[(size_t)(by + ty + j) * C + bx + tx];
    __syncthreads();
    #pragma unroll
    for (int j = 0; j < 32; j += 8)
        out[(size_t)(bx + ty + j) * R + by + tx] = __float2half_rn(t[tx][ty + j]);
}

__global__ __launch_bounds__(256) void transp_all(
    const float* wq, const float* wk, const float* wv, const float* wo,
    const float* w1, const float* w2,
    __half* wqT, __half* wkT, __half* wvT, __half* woT,
    __half* w1T, __half* w2T)
{
    int bid = blockIdx.x;   // 0..767
    if (bid < 256){         // four 256x256 weights, 64 tiles each (8x8)
        int m = bid >> 6, t = bid & 63;
        int bx = (t & 7) * 32, by = (t >> 3) * 32;
        const float* in  = (m==0)? wq : (m==1)? wk : (m==2)? wv : wo;
        __half*      outp= (m==0)? wqT: (m==1)? wkT: (m==2)? wvT: woT;
        transp_tile(in, outp, Dv, Dv, bx, by);
    } else if (bid < 512){  // w1: [Dv][DFFv] -> [DFFv][Dv], tiles (32 x, 8 y)
        int t = bid - 256;
        int bx = (t & 31) * 32, by = (t >> 5) * 32;
        transp_tile(w1, w1T, Dv, DFFv, bx, by);
    } else {                // w2: [DFFv][Dv] -> [Dv][DFFv], tiles (8 x, 32 y)
        int t = bid - 512;
        int bx = (t & 7) * 32, by = (t >> 3) * 32;
        transp_tile(w2, w2T, DFFv, Dv, bx, by);
    }
}

// ---------------- fp16 GEMM, cp.async double-buffered --------------------------
// BM=128 BN=64 BK=32, 8 warps (4m x 2n), warp tile 32x32, mma m16n8k16.
// W pre-transposed: Bt[n][k].
template<bool RELU, bool HOUT>
__global__ __launch_bounds__(256) void gemm_h(
    const __half* __restrict__ A, const __half* __restrict__ Bt,
    const float* __restrict__ bias, const float* __restrict__ res,
    float* __restrict__ Yf, __half* __restrict__ Yh, int M, int N, int K)
{
    __shared__ __half As[2][128*40];
    __shared__ __half Bs[2][64*40];

    const int tid  = threadIdx.x;
    const int lane = tid & 31;
    const int gid  = lane >> 2, tig = lane & 3;
    const int wid  = tid >> 5;
    const int wm   = wid >> 1, wn = wid & 1;
    const int bm   = blockIdx.y * 128, bn = blockIdx.x * 64;

    float acc[2][4][4];
    #pragma unroll
    for (int i = 0; i < 2; i++)
        #pragma unroll
        for (int j = 0; j < 4; j++)
            #pragma unroll
            for (int k = 0; k < 4; k++) acc[i][j][k] = 0.f;

    const int ar  = tid >> 2;           // A row 0..63 (+64)
    const int ac  = (tid & 3) * 8;      // A col chunk (8 halves = 16B)
    const int bn_ = tid >> 2;           // B n row 0..63
    const int bc  = (tid & 3) * 8;      // B k chunk

    auto stage = [&](int k0, int st){
        #pragma unroll
        for (int ir = 0; ir < 2; ir++){
            int r = ar + ir * 64;
            cpa16(&As[st][r * 40 + ac], A + (size_t)(bm + r) * K + k0 + ac);
        }
        cpa16(&Bs[st][bn_ * 40 + bc], Bt + (size_t)(bn + bn_) * K + k0 + bc);
        cpa_commit();
    };

    stage(0, 0);
    int buf = 0;
    for (int k0 = 0; k0 < K; k0 += 32){
        bool nxt = (k0 + 32 < K);
        if (nxt) stage(k0 + 32, buf ^ 1);
        if (nxt) cpa_wait<1>(); else cpa_wait<0>();
        __syncthreads();

        const __half* Ab = As[buf];
        const __half* Bb = Bs[buf];
        #pragma unroll
        for (int ks = 0; ks < 2; ks++){
            const int kc = ks * 16 + 2 * tig;
            uint32_t af[2][4];
            #pragma unroll
            for (int mt = 0; mt < 2; mt++){
                const __half* base = &Ab[(wm*32 + mt*16 + gid) * 40 + kc];
                af[mt][0] = lds32(base);
                af[mt][1] = lds32(base + 8*40);
                af[mt][2] = lds32(base + 8);
                af[mt][3] = lds32(base + 8*40 + 8);
            }
            #pragma unroll
            for (int nt = 0; nt < 4; nt++){
                const __half* nb = &Bb[(wn*32 + nt*8 + gid) * 40 + kc];
                uint32_t b0 = lds32(nb);
                uint32_t b1 = lds32(nb + 8);
                #pragma unroll
                for (int mt = 0; mt < 2; mt++)
                    mma_f16(acc[mt][nt], af[mt], b0, b1);
            }
        }
        __syncthreads();
        buf ^= 1;
    }

    #pragma unroll
    for (int mt = 0; mt < 2; mt++){
        #pragma unroll
        for (int nt = 0; nt < 4; nt++){
            int col = bn + wn * 32 + nt * 8 + 2 * tig;
            float b0 = bias[col], b1 = bias[col + 1];
            int r0 = bm + wm * 32 + mt * 16 + gid;
            #pragma unroll
            for (int hf = 0; hf < 2; hf++){
                int row = r0 + hf * 8;
                float v0 = acc[mt][nt][hf*2+0] + b0;
                float v1 = acc[mt][nt][hf*2+1] + b1;
                if (res){
                    v0 += res[(size_t)row * N + col];
                    v1 += res[(size_t)row * N + col + 1];
                }
                if (RELU){ v0 = fmaxf(v0, 0.f); v1 = fmaxf(v1, 0.f); }
                if (HOUT){
                    __half2 hv = __floats2half2_rn(v0, v1);
                    *reinterpret_cast<__half2*>(Yh + (size_t)row * N + col) = hv;
                } else {
                    *reinterpret_cast<float2*>(Yf + (size_t)row * N + col) = make_float2(v0, v1);
                }
            }
        }
    }
}

// ---------------- flash attention, cp.async double-buffered --------------------
// CTA: 128 queries of one (b,h); 8 warps x 16 rows; 32 key-tiles of 128.
#define KST  72
#define VTST 136
#define NT_TILES (Sv/128)
// smem: sQ(128*72) + 2*sK(128*72) + 2*sVr(128*72) + sVT(64*136) + 2*mask(128 f32)
#define ATTN_SMEM_BYTES (128*KST*2*5 + 64*VTST*2 + 2*128*4)

__global__ __launch_bounds__(256, 2) void attn_h(
    const __half* __restrict__ Q, const __half* __restrict__ K,
    const __half* __restrict__ V, const float* __restrict__ mask,
    __half* __restrict__ O)
{
    extern __shared__ char smem_raw[];
    __half* sQ  = reinterpret_cast<__half*>(smem_raw);
    __half* sK0 = sQ  + 128*KST;
    __half* sK1 = sK0 + 128*KST;
    __half* sV0 = sK1 + 128*KST;
    __half* sV1 = sV0 + 128*KST;
    __half* sVT = sV1 + 128*KST;
    float* sMask0 = reinterpret_cast<float*>(sVT + 64*VTST);
    float* sMask1 = sMask0 + 128;

    const int tid = threadIdx.x, lane = tid & 31, wid = tid >> 5;
    const int gid = lane >> 2, tig = lane & 3;
    const int m0  = wid * 16;
    const int b   = blockIdx.y >> 2, h = blockIdx.y & 3;
    const int q0  = blockIdx.x * 128;
    const __half* Qb = Q + (size_t)b*Sv*Dv + (size_t)h*DEP;
    const __half* Kb = K + (size_t)b*Sv*Dv + (size_t)h*DEP;
    const __half* Vb = V + (size_t)b*Sv*Dv + (size_t)h*DEP;
    const float*  Mb = mask + (size_t)b*Sv;

    const int sr  = tid >> 2;            // staging row 0..63 (+64)
    const int sc  = (tid & 3) * 16;      // staging col (16 halves = 32B, two 16B)

    auto stageKVM = [&](int kt, __half* dK, __half* dV, float* dM){
        const int kbase = kt * 128;
        #pragma unroll
        for (int ir = 0; ir < 2; ir++){
            int row = sr + ir * 64;
            const __half* ks_ = Kb + (size_t)(kbase + row) * Dv + sc;
            cpa16(&dK[row*KST + sc    ], ks_);
            cpa16(&dK[row*KST + sc + 8], ks_ + 8);
            const __half* vs_ = Vb + (size_t)(kbase + row) * Dv + sc;
            cpa16(&dV[row*KST + sc    ], vs_);
            cpa16(&dV[row*KST + sc + 8], vs_ + 8);
        }
        if (tid < 32) cpa16(&dM[tid*4], Mb + kbase + tid*4);
    };

    // prologue: Q + tile0 as group0
    {
        #pragma unroll
        for (int ir = 0; ir < 2; ir++){
            int row = sr + ir * 64;
            const __half* src = Qb + (size_t)(q0 + row) * Dv + sc;
            cpa16(&sQ[row*KST + sc    ], src);
            cpa16(&sQ[row*KST + sc + 8], src + 8);
        }
        stageKVM(0, sK0, sV0, sMask0);
        cpa_commit();
    }
    cpa_wait<0>();
    __syncthreads();

    // Q fragments cached in registers (4 k16 steps over d=64)
    uint32_t qf[4][4];
    #pragma unroll
    for (int kd = 0; kd < 4; kd++){
        const __half* base = &sQ[(m0 + gid)*KST + kd*16 + 2*tig];
        qf[kd][0] = lds32(base);
        qf[kd][1] = lds32(base + 8*KST);
        qf[kd][2] = lds32(base + 8);
        qf[kd][3] = lds32(base + 8*KST + 8);
    }

    float o[8][4];
    #pragma unroll
    for (int i = 0; i < 8; i++){ o[i][0]=o[i][1]=o[i][2]=o[i][3]=0.f; }
    float mrow[2] = {-1e30f, -1e30f};
    float lrow[2] = {0.f, 0.f};

    const int vkp = tid & 63;            // V-transpose key pair
    const int vdb = (tid >> 6) * 8;      // V-transpose d base

    for (int kt = 0; kt < NT_TILES; kt++){
        const int buf = kt & 1;
        __half* cK = buf ? sK1 : sK0;
        __half* cV = buf ? sV1 : sV0;
        float*  cM = buf ? sMask1 : sMask0;
        const bool nxt = (kt + 1 < NT_TILES);
        if (nxt){
            stageKVM(kt + 1, buf ? sK0 : sK1, buf ? sV0 : sV1,
                     buf ? sMask0 : sMask1);
            cpa_commit();
        }

        // transpose V: sVr[buf] -> sVT[d][key]
        #pragma unroll
        for (int it = 0; it < 2; it++){
            int d0 = vdb + it * 32;
            uint4 va = *reinterpret_cast<const uint4*>(&cV[(2*vkp    )*KST + d0]);
            uint4 vb = *reinterpret_cast<const uint4*>(&cV[(2*vkp + 1)*KST + d0]);
            const __half* ha = reinterpret_cast<const __half*>(&va);
            const __half* hb = reinterpret_cast<const __half*>(&vb);
            #pragma unroll
            for (int j = 0; j < 8; j++){
                __half2 pr = __halves2half2(ha[j], hb[j]);
                *reinterpret_cast<uint32_t*>(&sVT[(d0+j)*VTST + 2*vkp]) =
                    *reinterpret_cast<uint32_t*>(&pr);
            }
        }

        // ---- S = Q @ K^T over full 128 keys (two 64-key halves) ----
        float p[2][8][4];
        #pragma unroll
        for (int hh2 = 0; hh2 < 2; hh2++)
            #pragma unroll
            for (int nt = 0; nt < 8; nt++){
                p[hh2][nt][0]=p[hh2][nt][1]=p[hh2][nt][2]=p[hh2][nt][3]=0.f;
            }
        #pragma unroll
        for (int hh2 = 0; hh2 < 2; hh2++){
            const int kh0 = hh2 * 64;
            #pragma unroll
            for (int kd = 0; kd < 4; kd++){
                #pragma unroll
                for (int nt = 0; nt < 8; nt++){
                    const __half* kbp = &cK[(kh0 + nt*8 + gid)*KST + kd*16 + 2*tig];
                    uint32_t b0 = lds32(kbp);
                    uint32_t b1 = lds32(kbp + 8);
                    mma_f16(p[hh2][nt], qf[kd], b0, b1);
                }
            }
        }
        __syncthreads();      // sVT writes visible before PV reads

        // ---- softmax over 128 keys ----
        float rmax[2] = {-1e30f, -1e30f};
        #pragma unroll
        for (int hh2 = 0; hh2 < 2; hh2++){
            #pragma unroll
            for (int nt = 0; nt < 8; nt++){
                #pragma unroll
                for (int j = 0; j < 4; j++){
                    int key = hh2*64 + nt*8 + 2*tig + (j & 1);
                    float s = p[hh2][nt][j] * 0.125f - 1e9f * cM[key];
                    p[hh2][nt][j] = s;
                    rmax[j>>1] = fmaxf(rmax[j>>1], s);
                }
            }
        }
        #pragma unroll
        for (int hh = 0; hh < 2; hh++){
            rmax[hh] = fmaxf(rmax[hh], __shfl_xor_sync(0xffffffffu, rmax[hh], 1));
            rmax[hh] = fmaxf(rmax[hh], __shfl_xor_sync(0xffffffffu, rmax[hh], 2));
        }
        float mnew[2], alpha[2], rsum[2];
        #pragma unroll
        for (int hh = 0; hh < 2; hh++){
            mnew[hh]  = fmaxf(mrow[hh], rmax[hh]);
            alpha[hh] = __expf(mrow[hh] - mnew[hh]);
            rsum[hh]  = 0.f;
        }
        #pragma unroll
        for (int hh2 = 0; hh2 < 2; hh2++)
            #pragma unroll
            for (int nt = 0; nt < 8; nt++)
                #pragma unroll
                for (int j = 0; j < 4; j++){
                    float e = __expf(p[hh2][nt][j] - mnew[j>>1]);
                    p[hh2][nt][j] = e;
                    rsum[j>>1] += e;
                }
        #pragma unroll
        for (int hh = 0; hh < 2; hh++){
            rsum[hh] += __shfl_xor_sync(0xffffffffu, rsum[hh], 1);
            rsum[hh] += __shfl_xor_sync(0xffffffffu, rsum[hh], 2);
            lrow[hh] = lrow[hh] * alpha[hh] + rsum[hh];
            mrow[hh] = mnew[hh];
        }
        #pragma unroll
        for (int nt = 0; nt < 8; nt++){
            o[nt][0] *= alpha[0]; o[nt][1] *= alpha[0];
            o[nt][2] *= alpha[1]; o[nt][3] *= alpha[1];
        }

        // ---- O += P @ V over 128 keys ----
        #pragma unroll
        for (int hh2 = 0; hh2 < 2; hh2++){
            const int kh0 = hh2 * 64;
            #pragma unroll
            for (int ks = 0; ks < 4; ks++){
                uint32_t ap[4];
                ap[0] = pack2(p[hh2][2*ks  ][0], p[hh2][2*ks  ][1]);
                ap[1] = pack2(p[hh2][2*ks  ][2], p[hh2][2*ks  ][3]);
                ap[2] = pack2(p[hh2][2*ks+1][0], p[hh2][2*ks+1][1]);
                ap[3] = pack2(p[hh2][2*ks+1][2], p[hh2][2*ks+1][3]);
                #pragma unroll
                for (int nt = 0; nt < 8; nt++){
                    const __half* vbp = &sVT[(nt*8 + gid)*VTST + kh0 + ks*16 + 2*tig];
                    uint32_t b0 = lds32(vbp);
                    uint32_t b1 = lds32(vbp + 8);
                    mma_f16(o[nt], ap, b0, b1);
                }
            }
        }
        if (nxt) cpa_wait<0>();
        __syncthreads();      // all reads of this stage done; next tile visible
    }

    float inv0 = 1.f / lrow[0], inv1 = 1.f / lrow[1];
    #pragma unroll
    for (int nt = 0; nt < 8; nt++){
        int col  = h * DEP + nt * 8 + 2 * tig;
        int row0 = q0 + m0 + gid;
        __half2 h0 = __floats2half2_rn(o[nt][0]*inv0, o[nt][1]*inv0);
        __half2 h1 = __floats2half2_rn(o[nt][2]*inv1, o[nt][3]*inv1);
        *reinterpret_cast<__half2*>(O + (size_t)(b*Sv + row0    )*Dv + col) = h0;
        *reinterpret_cast<__half2*>(O + (size_t)(b*Sv + row0 + 8)*Dv + col) = h1;
    }
}

// ---------------- LayerNorm: warp per row, no block barriers -------------------
__global__ __launch_bounds__(256) void ln_kernel(
    const float* __restrict__ in, float* __restrict__ out, __half* __restrict__ outh,
    const float* __restrict__ g, const float* __restrict__ bt,
    int N, float eps)
{
    const int lane = threadIdx.x & 31;
    const int row  = blockIdx.x * 8 + (threadIdx.x >> 5);
    const int nch  = N >> 7;                 // float4-chunks of 128 per row: 2 or 8
    const float* x = in + (size_t)row * N;

    float4 v[8];
    float s = 0.f;
    for (int j = 0; j < nch; j++){
        v[j] = *reinterpret_cast<const float4*>(x + j*128 + lane*4);
        s += v[j].x + v[j].y + v[j].z + v[j].w;
    }
    #pragma unroll
    for (int o = 16; o; o >>= 1) s += __shfl_xor_sync(0xffffffffu, s, o);
    float mu = s / N;
    float var = 0.f;
    for (int j = 0; j < nch; j++){
        float dx = v[j].x-mu, dy = v[j].y-mu, dz = v[j].z-mu, dw = v[j].w-mu;
        var += dx*dx + dy*dy + dz*dz + dw*dw;
    }
    #pragma unroll
    for (int o = 16; o; o >>= 1) var += __shfl_xor_sync(0xffffffffu, var, o);
    float rstd = rsqrtf(var / N + eps);

    for (int j = 0; j < nch; j++){
        int c = j*128 + lane*4;
        float4 gg = *reinterpret_cast<const float4*>(g  + c);
        float4 bb = *reinterpret_cast<const float4*>(bt + c);
        float y0 = (v[j].x - mu) * rstd * gg.x + bb.x;
        float y1 = (v[j].y - mu) * rstd * gg.y + bb.y;
        float y2 = (v[j].z - mu) * rstd * gg.z + bb.z;
        float y3 = (v[j].w - mu) * rstd * gg.w + bb.w;
        if (out)
            *reinterpret_cast<float4*>(out + (size_t)row * N + c) =
                make_float4(y0, y1, y2, y3);
        if (outh){
            uint2 u;
            u.x = pack2(y0, y1);
            u.y = pack2(y2, y3);
            *reinterpret_cast<uint2*>(outh + (size_t)row * N + c) = u;
        }
    }
}

// ---------------- launch --------------------------------------------------------
extern "C" void kernel_launch(void* const* d_in, const int* in_sizes, int n_in,
                              void* d_out, int out_size)
{
    (void)in_sizes; (void)n_in; (void)out_size;
    const float* x    = (const float*)d_in[0];
    const float* mask = (const float*)d_in[1];
    const float* wq   = (const float*)d_in[2];
    const float* bq   = (const float*)d_in[3];
    const float* wk   = (const float*)d_in[4];
    const float* bk   = (const float*)d_in[5];
    const float* wv   = (const float*)d_in[6];
    const float* bv   = (const float*)d_in[7];
    const float* wo   = (const float*)d_in[8];
    const float* bo   = (const float*)d_in[9];
    const float* w1   = (const float*)d_in[10];
    const float* b1   = (const float*)d_in[11];
    const float* lnffg= (const float*)d_in[12];
    const float* lnffb= (const float*)d_in[13];
    const float* w2   = (const float*)d_in[14];
    const float* b2   = (const float*)d_in[15];
    const float* ln1g = (const float*)d_in[16];
    const float* ln1b = (const float*)d_in[17];
    const float* ln2g = (const float*)d_in[18];
    const float* ln2b = (const float*)d_in[19];
    float* out = (float*)d_out;

    float  *X1, *Hb;
    __half *xh, *Qh, *Kh, *Vh, *ctxh, *x1h, *hh;
    __half *wqT, *wkT, *wvT, *woT, *w1T, *w2T;
    cudaGetSymbolAddress((void**)&X1,   g_X1);
    cudaGetSymbolAddress((void**)&Hb,   g_H);
    cudaGetSymbolAddress((void**)&xh,   g_xh);
    cudaGetSymbolAddress((void**)&Qh,   g_Qh);
    cudaGetSymbolAddress((void**)&Kh,   g_Kh);
    cudaGetSymbolAddress((void**)&Vh,   g_Vh);
    cudaGetSymbolAddress((void**)&ctxh, g_ctxh);
    cudaGetSymbolAddress((void**)&x1h,  g_x1h);
    cudaGetSymbolAddress((void**)&hh,   g_hh);
    cudaGetSymbolAddress((void**)&wqT,  g_wqT);
    cudaGetSymbolAddress((void**)&wkT,  g_wkT);
    cudaGetSymbolAddress((void**)&wvT,  g_wvT);
    cudaGetSymbolAddress((void**)&woT,  g_woT);
    cudaGetSymbolAddress((void**)&w1T,  g_w1T);
    cudaGetSymbolAddress((void**)&w2T,  g_w2T);

    cudaFuncSetAttribute(attn_h, cudaFuncAttributeMaxDynamicSharedMemorySize,
                         ATTN_SMEM_BYTES);

    const dim3 blk(256);
    const dim3 gP(Dv/64,   MTOK/128);
    const dim3 gF(DFFv/64, MTOK/128);

    // launch 1: x -> fp16
    cvt_kernel<<<(MTOK*Dv/4 + 255)/256, blk>>>(x, xh, MTOK*Dv/4);
    // launch 2: all weight transposes
    transp_all<<<768, dim3(32,8)>>>(wq, wk, wv, wo, w1, w2,
                                    wqT, wkT, wvT, woT, w1T, w2T);
    // launches 3-5: QKV projections
    gemm_h<false,true><<<gP, blk>>>(xh, wqT, bq, nullptr, nullptr, Qh, MTOK, Dv, Dv);
    gemm_h<false,true><<<gP, blk>>>(xh, wkT, bk, nullptr, nullptr, Kh, MTOK, Dv, Dv);
    gemm_h<false,true><<<gP, blk>>>(xh, wvT, bv, nullptr, nullptr, Vh, MTOK, Dv, Dv);
    // launch 6: attention (profiled by ncu -s 5 -c 1)
    attn_h<<<dim3(Sv/128, Bv*Hv), blk, ATTN_SMEM_BYTES>>>(Qh, Kh, Vh, mask, ctxh);
    // out-proj + residual, LN1
    gemm_h<false,false><<<gP, blk>>>(ctxh, woT, bo, x, X1, nullptr, MTOK, Dv, Dv);
    ln_kernel<<<MTOK/8, blk>>>(X1, X1, x1h, ln1g, ln1b, Dv, 1e-3f);
    // FFN1 + relu, LN_ff
    gemm_h<true,false><<<gF, blk>>>(x1h, w1T, b1, nullptr, Hb, nullptr, MTOK, DFFv, Dv);
    ln_kernel<<<MTOK/8, blk>>>(Hb, nullptr, hh, lnffg, lnffb, DFFv, 1e-6f);
    // FFN2 + residual, LN2
    gemm_h<false,false><<<gP, blk>>>(hh, w2T, b2, X1, out, nullptr, MTOK, Dv, DFFv);
    ln_kernel<<<MTOK/8, blk>>>(out, out, nullptr, ln2g, ln2b, Dv, 1e-3f);
}

// round 6
// speedup vs baseline: 2.1424x; 1.0210x over previous
#include <cuda_runtime.h>
#include <cuda_fp16.h>
#include <cstdint>
#include <cstddef>

#define Bv   4
#define Sv   4096
#define Dv   256
#define Hv   4
#define DEP  64
#define DFFv 1024
#define MTOK (Bv*Sv)
#define NQKV (3*Dv)

// ---------------- scratch (device globals) ------------------------------------
__device__ float  g_X1[MTOK*Dv];
__device__ float  g_H [(size_t)MTOK*DFFv];
__device__ float  g_negm[Bv*Sv];
__device__ float  g_bqkv[NQKV];
__device__ __half g_xh   [MTOK*Dv];
__device__ __half g_QKVh [(size_t)MTOK*NQKV];
__device__ __half g_ctxh [MTOK*Dv];
__device__ __half g_x1h  [MTOK*Dv];
__device__ __half g_hh   [(size_t)MTOK*DFFv];
__device__ __half g_wqkvT[(size_t)NQKV*Dv];
__device__ __half g_woT[Dv*Dv];
__device__ __half g_w1T[(size_t)DFFv*Dv];
__device__ __half g_w2T[(size_t)Dv*DFFv];

// ---------------- helpers ------------------------------------------------------
__device__ __forceinline__ uint32_t sm32(const void* p){
    return (uint32_t)__cvta_generic_to_shared(p);
}
__device__ __forceinline__ void cpa16(void* s, const void* g){
    asm volatile("cp.async.cg.shared.global [%0], [%1], 16;"
                 :: "r"(sm32(s)), "l"(g));
}
__device__ __forceinline__ void cpa_commit(){
    asm volatile("cp.async.commit_group;");
}
template<int N> __device__ __forceinline__ void cpa_wait(){
    asm volatile("cp.async.wait_group %0;" :: "n"(N));
}
__device__ __forceinline__ void mma_f16(float* c, const uint32_t* a,
                                        uint32_t b0, uint32_t b1){
    asm volatile(
      "mma.sync.aligned.m16n8k16.row.col.f32.f16.f16.f32 "
      "{%0,%1,%2,%3},{%4,%5,%6,%7},{%8,%9},{%0,%1,%2,%3};\n"
      : "+f"(c[0]), "+f"(c[1]), "+f"(c[2]), "+f"(c[3])
      : "r"(a[0]), "r"(a[1]), "r"(a[2]), "r"(a[3]), "r"(b0), "r"(b1));
}
__device__ __forceinline__ uint32_t pack2(float a, float b){
    __half2 h = __floats2half2_rn(a, b);
    return *reinterpret_cast<uint32_t*>(&h);
}
__device__ __forceinline__ uint32_t lds32(const __half* p){
    return *reinterpret_cast<const uint32_t*>(p);
}

// ---------------- prep: fp32 -> fp16 -------------------------------------------
__global__ __launch_bounds__(256) void cvt_kernel(
    const float* __restrict__ in, __half* __restrict__ out, int n4)
{
    int i = blockIdx.x * blockDim.x + threadIdx.x;
    if (i < n4){
        float4 v = reinterpret_cast<const float4*>(in)[i];
        uint2 u;
        u.x = pack2(v.x, v.y);
        u.y = pack2(v.z, v.w);
        reinterpret_cast<uint2*>(out)[i] = u;
    }
}

// ---------------- prep: concat qkv bias + premultiplied mask -------------------
__global__ __launch_bounds__(256) void prep_kernel(
    const float* __restrict__ bq, const float* __restrict__ bk,
    const float* __restrict__ bv, const float* __restrict__ mask,
    float* __restrict__ bqkv, float* __restrict__ negm)
{
    int i = blockIdx.x * blockDim.x + threadIdx.x;
    if (i < NQKV)
        bqkv[i] = (i < Dv) ? bq[i] : (i < 2*Dv) ? bk[i - Dv] : bv[i - 2*Dv];
    int j = i - NQKV;
    if (j >= 0 && j < Bv*Sv)
        negm[j] = -1e9f * mask[j];
}

// ---------------- prep: all weight transposes ----------------------------------
__device__ __forceinline__ void transp_tile(
    const float* __restrict__ in, __half* __restrict__ out,
    int R, int C, int bx, int by)
{
    __shared__ float t[32][33];
    int tx = threadIdx.x, ty = threadIdx.y;         // block (32,8)
    #pragma unroll
    for (int j = 0; j < 32; j += 8)
        t[ty + j][tx] = in[(size_t)(by + ty + j) * C + bx + tx];
    __syncthreads();
    #pragma unroll
    for (int j = 0; j < 32; j += 8)
        out[(size_t)(bx + ty + j) * R + by + tx] = __float2half_rn(t[tx][ty + j]);
}

__global__ __launch_bounds__(256) void transp_all(
    const float* wq, const float* wk, const float* wv, const float* wo,
    const float* w1, const float* w2,
    __half* wqkvT, __half* woT, __half* w1T, __half* w2T)
{
    int bid = blockIdx.x;   // 0..767
    if (bid < 256){         // four 256x256 weights, 64 tiles each (8x8)
        int m = bid >> 6, t = bid & 63;
        int bx = (t & 7) * 32, by = (t >> 3) * 32;
        const float* in  = (m==0)? wq : (m==1)? wk : (m==2)? wv : wo;
        __half*      outp= (m==3)? woT : wqkvT + (size_t)m * Dv * Dv;
        transp_tile(in, outp, Dv, Dv, bx, by);
    } else if (bid < 512){  // w1: [Dv][DFFv] -> [DFFv][Dv]
        int t = bid - 256;
        int bx = (t & 31) * 32, by = (t >> 5) * 32;
        transp_tile(w1, w1T, Dv, DFFv, bx, by);
    } else {                // w2: [DFFv][Dv] -> [Dv][DFFv]
        int t = bid - 512;
        int bx = (t & 7) * 32, by = (t >> 3) * 32;
        transp_tile(w2, w2T, DFFv, Dv, bx, by);
    }
}

// ---------------- fp16 GEMM, 3-stage cp.async ring, single sync per iter -------
// BM=128 BN=64 BK=32, 8 warps (4m x 2n), warp tile 32x32, mma m16n8k16.
template<bool RELU, bool HOUT>
__global__ __launch_bounds__(256) void gemm_h(
    const __half* __restrict__ A, const __half* __restrict__ Bt,
    const float* __restrict__ bias, const float* __restrict__ res,
    float* __restrict__ Yf, __half* __restrict__ Yh, int M, int N, int K)
{
    __shared__ __half As[3][128*40];
    __shared__ __half Bs[3][64*40];

    const int tid  = threadIdx.x;
    const int lane = tid & 31;
    const int gid  = lane >> 2, tig = lane & 3;
    const int wid  = tid >> 5;
    const int wm   = wid >> 1, wn = wid & 1;
    const int bm   = blockIdx.y * 128, bn = blockIdx.x * 64;

    float acc[2][4][4];
    #pragma unroll
    for (int i = 0; i < 2; i++)
        #pragma unroll
        for (int j = 0; j < 4; j++)
            #pragma unroll
            for (int k = 0; k < 4; k++) acc[i][j][k] = 0.f;

    const int ar  = tid >> 2;           // A row 0..63 (+64)
    const int ac  = (tid & 3) * 8;      // A col chunk (16B)
    const int bn_ = tid >> 2;           // B n row 0..63
    const int bc  = (tid & 3) * 8;      // B k chunk

    auto stage = [&](int k0, int st){
        #pragma unroll
        for (int ir = 0; ir < 2; ir++){
            int r = ar + ir * 64;
            cpa16(&As[st][r * 40 + ac], A + (size_t)(bm + r) * K + k0 + ac);
        }
        cpa16(&Bs[st][bn_ * 40 + bc], Bt + (size_t)(bn + bn_) * K + k0 + bc);
        cpa_commit();
    };

    const int KIT = K >> 5;
    stage(0, 0);
    stage(32, 1);

    for (int it = 0; it < KIT; it++){
        if (it + 1 < KIT) cpa_wait<1>(); else cpa_wait<0>();
        __syncthreads();
        if (it + 2 < KIT) stage((it + 2) * 32, (it + 2) % 3);

        const __half* Ab = As[it % 3];
        const __half* Bb = Bs[it % 3];
        #pragma unroll
        for (int ks = 0; ks < 2; ks++){
            const int kc = ks * 16 + 2 * tig;
            uint32_t af[2][4];
            #pragma unroll
            for (int mt = 0; mt < 2; mt++){
                const __half* base = &Ab[(wm*32 + mt*16 + gid) * 40 + kc];
                af[mt][0] = lds32(base);
                af[mt][1] = lds32(base + 8*40);
                af[mt][2] = lds32(base + 8);
                af[mt][3] = lds32(base + 8*40 + 8);
            }
            #pragma unroll
            for (int nt = 0; nt < 4; nt++){
                const __half* nb = &Bb[(wn*32 + nt*8 + gid) * 40 + kc];
                uint32_t b0 = lds32(nb);
                uint32_t b1 = lds32(nb + 8);
                #pragma unroll
                for (int mt = 0; mt < 2; mt++)
                    mma_f16(acc[mt][nt], af[mt], b0, b1);
            }
        }
    }

    #pragma unroll
    for (int mt = 0; mt < 2; mt++){
        #pragma unroll
        for (int nt = 0; nt < 4; nt++){
            int col = bn + wn * 32 + nt * 8 + 2 * tig;
            float b0 = bias[col], b1 = bias[col + 1];
            int r0 = bm + wm * 32 + mt * 16 + gid;
            #pragma unroll
            for (int hf = 0; hf < 2; hf++){
                int row = r0 + hf * 8;
                float v0 = acc[mt][nt][hf*2+0] + b0;
                float v1 = acc[mt][nt][hf*2+1] + b1;
                if (res){
                    v0 += res[(size_t)row * N + col];
                    v1 += res[(size_t)row * N + col + 1];
                }
                if (RELU){ v0 = fmaxf(v0, 0.f); v1 = fmaxf(v1, 0.f); }
                if (HOUT){
                    __half2 hv = __floats2half2_rn(v0, v1);
                    *reinterpret_cast<__half2*>(Yh + (size_t)row * N + col) = hv;
                } else {
                    *reinterpret_cast<float2*>(Yf + (size_t)row * N + col) = make_float2(v0, v1);
                }
            }
        }
    }
}

// ---------------- flash attention: 64-key halves, 2 CTAs/SM --------------------
// CTA: 128 queries of one (b,h); 8 warps x 16 rows; 32 key-tiles of 128.
// Q/K/V read from fused QKV buffer (row stride NQKV).
#define KST  72
#define VTST 136
#define NT_TILES (Sv/128)
#define ATTN_SMEM_BYTES (128*KST*2*5 + 64*VTST*2 + 2*128*4)

__global__ __launch_bounds__(256, 2) void attn_h(
    const __half* __restrict__ QKV, const float* __restrict__ negm,
    __half* __restrict__ O)
{
    extern __shared__ char smem_raw[];
    __half* sQ  = reinterpret_cast<__half*>(smem_raw);
    __half* sK0 = sQ  + 128*KST;
    __half* sK1 = sK0 + 128*KST;
    __half* sV0 = sK1 + 128*KST;
    __half* sV1 = sV0 + 128*KST;
    __half* sVT = sV1 + 128*KST;
    float* sMask0 = reinterpret_cast<float*>(sVT + 64*VTST);
    float* sMask1 = sMask0 + 128;

    const int tid = threadIdx.x, lane = tid & 31, wid = tid >> 5;
    const int gid = lane >> 2, tig = lane & 3;
    const int m0  = wid * 16;
    const int b   = blockIdx.y >> 2, h = blockIdx.y & 3;
    const int q0  = blockIdx.x * 128;
    const __half* Qb = QKV + (size_t)b*Sv*NQKV + (size_t)h*DEP;
    const __half* Kb = Qb + Dv;
    const __half* Vb = Qb + 2*Dv;
    const float*  Mb = negm + (size_t)b*Sv;

    const int sr  = tid >> 2;            // staging row 0..63 (+64)
    const int sc  = (tid & 3) * 16;      // staging col (two 16B chunks)

    auto stageKVM = [&](int kt, __half* dK, __half* dV, float* dM){
        const int kbase = kt * 128;
        #pragma unroll
        for (int ir = 0; ir < 2; ir++){
            int row = sr + ir * 64;
            const __half* ks_ = Kb + (size_t)(kbase + row) * NQKV + sc;
            cpa16(&dK[row*KST + sc    ], ks_);
            cpa16(&dK[row*KST + sc + 8], ks_ + 8);
            const __half* vs_ = Vb + (size_t)(kbase + row) * NQKV + sc;
            cpa16(&dV[row*KST + sc    ], vs_);
            cpa16(&dV[row*KST + sc + 8], vs_ + 8);
        }
        if (tid < 32) cpa16(&dM[tid*4], Mb + kbase + tid*4);
    };

    // prologue: Q + tile0
    {
        #pragma unroll
        for (int ir = 0; ir < 2; ir++){
            int row = sr + ir * 64;
            const __half* src = Qb + (size_t)(q0 + row) * NQKV + sc;
            cpa16(&sQ[row*KST + sc    ], src);
            cpa16(&sQ[row*KST + sc + 8], src + 8);
        }
        stageKVM(0, sK0, sV0, sMask0);
        cpa_commit();
    }
    cpa_wait<0>();
    __syncthreads();

    uint32_t qf[4][4];
    #pragma unroll
    for (int kd = 0; kd < 4; kd++){
        const __half* base = &sQ[(m0 + gid)*KST + kd*16 + 2*tig];
        qf[kd][0] = lds32(base);
        qf[kd][1] = lds32(base + 8*KST);
        qf[kd][2] = lds32(base + 8);
        qf[kd][3] = lds32(base + 8*KST + 8);
    }

    float o[8][4];
    #pragma unroll
    for (int i = 0; i < 8; i++){ o[i][0]=o[i][1]=o[i][2]=o[i][3]=0.f; }
    float mrow[2] = {-1e30f, -1e30f};
    float lrow[2] = {0.f, 0.f};

    const int vkp = tid & 63;            // V-transpose key pair
    const int vdb = (tid >> 6) * 8;      // V-transpose d base

    for (int kt = 0; kt < NT_TILES; kt++){
        const int buf = kt & 1;
        __half* cK = buf ? sK1 : sK0;
        __half* cV = buf ? sV1 : sV0;
        float*  cM = buf ? sMask1 : sMask0;
        const bool nxt = (kt + 1 < NT_TILES);
        if (nxt){
            stageKVM(kt + 1, buf ? sK0 : sK1, buf ? sV0 : sV1,
                     buf ? sMask0 : sMask1);
            cpa_commit();
        }

        // transpose V: cV[key][d] -> sVT[d][key] (all 128 keys)
        #pragma unroll
        for (int it = 0; it < 2; it++){
            int d0 = vdb + it * 32;
            uint4 va = *reinterpret_cast<const uint4*>(&cV[(2*vkp    )*KST + d0]);
            uint4 vb = *reinterpret_cast<const uint4*>(&cV[(2*vkp + 1)*KST + d0]);
            const __half* ha = reinterpret_cast<const __half*>(&va);
            const __half* hb = reinterpret_cast<const __half*>(&vb);
            #pragma unroll
            for (int j = 0; j < 8; j++){
                __half2 pr = __halves2half2(ha[j], hb[j]);
                *reinterpret_cast<uint32_t*>(&sVT[(d0+j)*VTST + 2*vkp]) =
                    *reinterpret_cast<uint32_t*>(&pr);
            }
        }

        #pragma unroll
        for (int hh2 = 0; hh2 < 2; hh2++){
            const int kh0 = hh2 * 64;
            // ---- S = Q @ K^T over 64 keys ----
            float p[8][4];
            #pragma unroll
            for (int nt = 0; nt < 8; nt++){ p[nt][0]=p[nt][1]=p[nt][2]=p[nt][3]=0.f; }
            #pragma unroll
            for (int kd = 0; kd < 4; kd++){
                #pragma unroll
                for (int nt = 0; nt < 8; nt++){
                    const __half* kbp = &cK[(kh0 + nt*8 + gid)*KST + kd*16 + 2*tig];
                    uint32_t b0 = lds32(kbp);
                    uint32_t b1 = lds32(kbp + 8);
                    mma_f16(p[nt], qf[kd], b0, b1);
                }
            }
            if (hh2 == 0) __syncthreads();   // sVT + masks visible before use

            // ---- online softmax over this half ----
            float rmax[2] = {-1e30f, -1e30f};
            #pragma unroll
            for (int nt = 0; nt < 8; nt++){
                #pragma unroll
                for (int j = 0; j < 4; j++){
                    int key = kh0 + nt*8 + 2*tig + (j & 1);
                    float s = fmaf(p[nt][j], 0.125f, cM[key]);
                    p[nt][j] = s;
                    rmax[j>>1] = fmaxf(rmax[j>>1], s);
                }
            }
            #pragma unroll
            for (int hh = 0; hh < 2; hh++){
                rmax[hh] = fmaxf(rmax[hh], __shfl_xor_sync(0xffffffffu, rmax[hh], 1));
                rmax[hh] = fmaxf(rmax[hh], __shfl_xor_sync(0xffffffffu, rmax[hh], 2));
            }
            float mnew[2], alpha[2], rsum[2];
            #pragma unroll
            for (int hh = 0; hh < 2; hh++){
                mnew[hh]  = fmaxf(mrow[hh], rmax[hh]);
                alpha[hh] = __expf(mrow[hh] - mnew[hh]);
                rsum[hh]  = 0.f;
            }
            #pragma unroll
            for (int nt = 0; nt < 8; nt++){
                #pragma unroll
                for (int j = 0; j < 4; j++){
                    float e = __expf(p[nt][j] - mnew[j>>1]);
                    p[nt][j] = e;
                    rsum[j>>1] += e;
                }
            }
            #pragma unroll
            for (int hh = 0; hh < 2; hh++){
                rsum[hh] += __shfl_xor_sync(0xffffffffu, rsum[hh], 1);
                rsum[hh] += __shfl_xor_sync(0xffffffffu, rsum[hh], 2);
                lrow[hh] = lrow[hh] * alpha[hh] + rsum[hh];
                mrow[hh] = mnew[hh];
            }
            #pragma unroll
            for (int nt = 0; nt < 8; nt++){
                o[nt][0] *= alpha[0]; o[nt][1] *= alpha[0];
                o[nt][2] *= alpha[1]; o[nt][3] *= alpha[1];
            }
            // ---- O += P @ V over these 64 keys ----
            #pragma unroll
            for (int ks = 0; ks < 4; ks++){
                uint32_t ap[4];
                ap[0] = pack2(p[2*ks  ][0], p[2*ks  ][1]);
                ap[1] = pack2(p[2*ks  ][2], p[2*ks  ][3]);
                ap[2] = pack2(p[2*ks+1][0], p[2*ks+1][1]);
                ap[3] = pack2(p[2*ks+1][2], p[2*ks+1][3]);
                #pragma unroll
                for (int nt = 0; nt < 8; nt++){
                    const __half* vbp = &sVT[(nt*8 + gid)*VTST + kh0 + ks*16 + 2*tig];
                    uint32_t b0 = lds32(vbp);
                    uint32_t b1 = lds32(vbp + 8);
                    mma_f16(o[nt], ap, b0, b1);
                }
            }
        }
        if (nxt) cpa_wait<0>();
        __syncthreads();      // this tile fully consumed; next tile visible
    }

    float inv0 = 1.f / lrow[0], inv1 = 1.f / lrow[1];
    #pragma unroll
    for (int nt = 0; nt < 8; nt++){
        int col  = h * DEP + nt * 8 + 2 * tig;
        int row0 = q0 + m0 + gid;
        __half2 h0 = __floats2half2_rn(o[nt][0]*inv0, o[nt][1]*inv0);
        __half2 h1 = __floats2half2_rn(o[nt][2]*inv1, o[nt][3]*inv1);
        *reinterpret_cast<__half2*>(O + (size_t)(b*Sv + row0    )*Dv + col) = h0;
        *reinterpret_cast<__half2*>(O + (size_t)(b*Sv + row0 + 8)*Dv + col) = h1;
    }
}

// ---------------- LayerNorm: warp per row --------------------------------------
__global__ __launch_bounds__(256) void ln_kernel(
    const float* __restrict__ in, float* __restrict__ out, __half* __restrict__ outh,
    const float* __restrict__ g, const float* __restrict__ bt,
    int N, float eps)
{
    const int lane = threadIdx.x & 31;
    const int row  = blockIdx.x * 8 + (threadIdx.x >> 5);
    const int nch  = N >> 7;
    const float* x = in + (size_t)row * N;

    float4 v[8];
    float s = 0.f;
    for (int j = 0; j < nch; j++){
        v[j] = *reinterpret_cast<const float4*>(x + j*128 + lane*4);
        s += v[j].x + v[j].y + v[j].z + v[j].w;
    }
    #pragma unroll
    for (int o = 16; o; o >>= 1) s += __shfl_xor_sync(0xffffffffu, s, o);
    float mu = s / N;
    float var = 0.f;
    for (int j = 0; j < nch; j++){
        float dx = v[j].x-mu, dy = v[j].y-mu, dz = v[j].z-mu, dw = v[j].w-mu;
        var += dx*dx + dy*dy + dz*dz + dw*dw;
    }
    #pragma unroll
    for (int o = 16; o; o >>= 1) var += __shfl_xor_sync(0xffffffffu, var, o);
    float rstd = rsqrtf(var / N + eps);

    for (int j = 0; j < nch; j++){
        int c = j*128 + lane*4;
        float4 gg = *reinterpret_cast<const float4*>(g  + c);
        float4 bb = *reinterpret_cast<const float4*>(bt + c);
        float y0 = (v[j].x - mu) * rstd * gg.x + bb.x;
        float y1 = (v[j].y - mu) * rstd * gg.y + bb.y;
        float y2 = (v[j].z - mu) * rstd * gg.z + bb.z;
        float y3 = (v[j].w - mu) * rstd * gg.w + bb.w;
        if (out)
            *reinterpret_cast<float4*>(out + (size_t)row * N + c) =
                make_float4(y0, y1, y2, y3);
        if (outh){
            uint2 u;
            u.x = pack2(y0, y1);
            u.y = pack2(y2, y3);
            *reinterpret_cast<uint2*>(outh + (size_t)row * N + c) = u;
        }
    }
}

// ---------------- launch --------------------------------------------------------
extern "C" void kernel_launch(void* const* d_in, const int* in_sizes, int n_in,
                              void* d_out, int out_size)
{
    (void)in_sizes; (void)n_in; (void)out_size;
    const float* x    = (const float*)d_in[0];
    const float* mask = (const float*)d_in[1];
    const float* wq   = (const float*)d_in[2];
    const float* bq   = (const float*)d_in[3];
    const float* wk   = (const float*)d_in[4];
    const float* bk   = (const float*)d_in[5];
    const float* wv   = (const float*)d_in[6];
    const float* bv   = (const float*)d_in[7];
    const float* wo   = (const float*)d_in[8];
    const float* bo   = (const float*)d_in[9];
    const float* w1   = (const float*)d_in[10];
    const float* b1   = (const float*)d_in[11];
    const float* lnffg= (const float*)d_in[12];
    const float* lnffb= (const float*)d_in[13];
    const float* w2   = (const float*)d_in[14];
    const float* b2   = (const float*)d_in[15];
    const float* ln1g = (const float*)d_in[16];
    const float* ln1b = (const float*)d_in[17];
    const float* ln2g = (const float*)d_in[18];
    const float* ln2b = (const float*)d_in[19];
    float* out = (float*)d_out;

    float  *X1, *Hb, *negm, *bqkv;
    __half *xh, *QKVh, *ctxh, *x1h, *hh;
    __half *wqkvT, *woT, *w1T, *w2T;
    cudaGetSymbolAddress((void**)&X1,    g_X1);
    cudaGetSymbolAddress((void**)&Hb,    g_H);
    cudaGetSymbolAddress((void**)&negm,  g_negm);
    cudaGetSymbolAddress((void**)&bqkv,  g_bqkv);
    cudaGetSymbolAddress((void**)&xh,    g_xh);
    cudaGetSymbolAddress((void**)&QKVh,  g_QKVh);
    cudaGetSymbolAddress((void**)&ctxh,  g_ctxh);
    cudaGetSymbolAddress((void**)&x1h,   g_x1h);
    cudaGetSymbolAddress((void**)&hh,    g_hh);
    cudaGetSymbolAddress((void**)&wqkvT, g_wqkvT);
    cudaGetSymbolAddress((void**)&woT,   g_woT);
    cudaGetSymbolAddress((void**)&w1T,   g_w1T);
    cudaGetSymbolAddress((void**)&w2T,   g_w2T);

    cudaFuncSetAttribute(attn_h, cudaFuncAttributeMaxDynamicSharedMemorySize,
                         ATTN_SMEM_BYTES);

    const dim3 blk(256);
    const dim3 gQKV(NQKV/64, MTOK/128);
    const dim3 gP(Dv/64,    MTOK/128);
    const dim3 gF(DFFv/64,  MTOK/128);

    // prep
    cvt_kernel<<<(MTOK*Dv/4 + 255)/256, blk>>>(x, xh, MTOK*Dv/4);
    prep_kernel<<<(NQKV + Bv*Sv + 255)/256, blk>>>(bq, bk, bv, mask, bqkv, negm);
    transp_all<<<768, dim3(32,8)>>>(wq, wk, wv, wo, w1, w2,
                                    wqkvT, woT, w1T, w2T);
    // fused QKV projection
    gemm_h<false,true><<<gQKV, blk>>>(xh, wqkvT, bqkv, nullptr, nullptr, QKVh,
                                      MTOK, NQKV, Dv);
    // attention
    attn_h<<<dim3(Sv/128, Bv*Hv), blk, ATTN_SMEM_BYTES>>>(QKVh, negm, ctxh);
    // out-proj + residual, LN1
    gemm_h<false,false><<<gP, blk>>>(ctxh, woT, bo, x, X1, nullptr, MTOK, Dv, Dv);
    ln_kernel<<<MTOK/8, blk>>>(X1, X1, x1h, ln1g, ln1b, Dv, 1e-3f);
    // FFN1 + relu, LN_ff
    gemm_h<true,false><<<gF, blk>>>(x1h, w1T, b1, nullptr, Hb, nullptr, MTOK, DFFv, Dv);
    ln_kernel<<<MTOK/8, blk>>>(Hb, nullptr, hh, lnffg, lnffb, DFFv, 1e-6f);
    // FFN2 + residual, LN2
    gemm_h<false,false><<<gP, blk>>>(hh, w2T, b2, X1, out, nullptr, MTOK, Dv, DFFv);
    ln_kernel<<<MTOK/8, blk>>>(out, out, nullptr, ln2g, ln2b, Dv, 1e-3f);
}

// round 7
// speedup vs baseline: 2.3102x; 1.0783x over previous
#include <cuda_runtime.h>
#include <cuda_fp16.h>
#include <cstdint>
#include <cstddef>

#define Bv   4
#define Sv   4096
#define Dv   256
#define Hv   4
#define DEP  64
#define DFFv 1024
#define MTOK (Bv*Sv)
#define NQKV (3*Dv)

// ---------------- scratch (device globals) ------------------------------------
__device__ float  g_X1[MTOK*Dv];
__device__ float  g_H [(size_t)MTOK*DFFv];
__device__ float  g_negm[Bv*Sv];
__device__ float  g_bqkv[NQKV];
__device__ __half g_xh   [MTOK*Dv];
__device__ __half g_QKVh [(size_t)MTOK*NQKV];
__device__ __half g_ctxh [MTOK*Dv];
__device__ __half g_x1h  [MTOK*Dv];
__device__ __half g_hh   [(size_t)MTOK*DFFv];
__device__ __half g_wqkvT[(size_t)NQKV*Dv];
__device__ __half g_woT[Dv*Dv];
__device__ __half g_w1T[(size_t)DFFv*Dv];
__device__ __half g_w2T[(size_t)Dv*DFFv];

// ---------------- helpers ------------------------------------------------------
__device__ __forceinline__ uint32_t sm32(const void* p){
    return (uint32_t)__cvta_generic_to_shared(p);
}
__device__ __forceinline__ void cpa16(void* s, const void* g){
    asm volatile("cp.async.cg.shared.global [%0], [%1], 16;"
                 :: "r"(sm32(s)), "l"(g));
}
__device__ __forceinline__ void cpa_commit(){
    asm volatile("cp.async.commit_group;");
}
template<int N> __device__ __forceinline__ void cpa_wait(){
    asm volatile("cp.async.wait_group %0;" :: "n"(N));
}
__device__ __forceinline__ void mma_f16(float* c, const uint32_t* a,
                                        uint32_t b0, uint32_t b1){
    asm volatile(
      "mma.sync.aligned.m16n8k16.row.col.f32.f16.f16.f32 "
      "{%0,%1,%2,%3},{%4,%5,%6,%7},{%8,%9},{%0,%1,%2,%3};\n"
      : "+f"(c[0]), "+f"(c[1]), "+f"(c[2]), "+f"(c[3])
      : "r"(a[0]), "r"(a[1]), "r"(a[2]), "r"(a[3]), "r"(b0), "r"(b1));
}
__device__ __forceinline__ uint32_t pack2(float a, float b){
    __half2 h = __floats2half2_rn(a, b);
    return *reinterpret_cast<uint32_t*>(&h);
}
__device__ __forceinline__ uint32_t lds32(const __half* p){
    return *reinterpret_cast<const uint32_t*>(p);
}
__device__ __forceinline__ uint2 lds64(const __half* p){
    return *reinterpret_cast<const uint2*>(p);
}

// ---------------- prep: fp32 -> fp16 -------------------------------------------
__global__ __launch_bounds__(256) void cvt_kernel(
    const float* __restrict__ in, __half* __restrict__ out, int n4)
{
    int i = blockIdx.x * blockDim.x + threadIdx.x;
    if (i < n4){
        float4 v = reinterpret_cast<const float4*>(in)[i];
        uint2 u;
        u.x = pack2(v.x, v.y);
        u.y = pack2(v.z, v.w);
        reinterpret_cast<uint2*>(out)[i] = u;
    }
}

// ---------------- prep: concat qkv bias + premultiplied mask -------------------
__global__ __launch_bounds__(256) void prep_kernel(
    const float* __restrict__ bq, const float* __restrict__ bk,
    const float* __restrict__ bv, const float* __restrict__ mask,
    float* __restrict__ bqkv, float* __restrict__ negm)
{
    int i = blockIdx.x * blockDim.x + threadIdx.x;
    if (i < NQKV)
        bqkv[i] = (i < Dv) ? bq[i] : (i < 2*Dv) ? bk[i - Dv] : bv[i - 2*Dv];
    int j = i - NQKV;
    if (j >= 0 && j < Bv*Sv)
        negm[j] = -1e9f * mask[j];
}

// ---------------- prep: all weight transposes ----------------------------------
__device__ __forceinline__ void transp_tile(
    const float* __restrict__ in, __half* __restrict__ out,
    int R, int C, int bx, int by)
{
    __shared__ float t[32][33];
    int tx = threadIdx.x, ty = threadIdx.y;         // block (32,8)
    #pragma unroll
    for (int j = 0; j < 32; j += 8)
        t[ty + j][tx] = in[(size_t)(by + ty + j) * C + bx + tx];
    __syncthreads();
    #pragma unroll
    for (int j = 0; j < 32; j += 8)
        out[(size_t)(bx + ty + j) * R + by + tx] = __float2half_rn(t[tx][ty + j]);
}

__global__ __launch_bounds__(256) void transp_all(
    const float* wq, const float* wk, const float* wv, const float* wo,
    const float* w1, const float* w2,
    __half* wqkvT, __half* woT, __half* w1T, __half* w2T)
{
    int bid = blockIdx.x;   // 0..767
    if (bid < 256){
        int m = bid >> 6, t = bid & 63;
        int bx = (t & 7) * 32, by = (t >> 3) * 32;
        const float* in  = (m==0)? wq : (m==1)? wk : (m==2)? wv : wo;
        __half*      outp= (m==3)? woT : wqkvT + (size_t)m * Dv * Dv;
        transp_tile(in, outp, Dv, Dv, bx, by);
    } else if (bid < 512){
        int t = bid - 256;
        int bx = (t & 31) * 32, by = (t >> 5) * 32;
        transp_tile(w1, w1T, Dv, DFFv, bx, by);
    } else {
        int t = bid - 512;
        int bx = (t & 7) * 32, by = (t >> 3) * 32;
        transp_tile(w2, w2T, DFFv, Dv, bx, by);
    }
}

// ---------------- fp16 GEMM: 3-stage ring, LDS.64 k-interleaved fragments ------
// BM=128 BN=64 BK=32, 8 warps (4m x 2n), warp tile 32x32, mma m16n8k16.
// k-interleave: lane tig reads k-halves [4tig..4tig+3] for BOTH A and B -> mma
// k-sum invariant under the shared permutation.
#define GST 80
#define GEMM_SMEM_BYTES ((3*128*GST + 3*64*GST)*2)

template<bool RELU, bool HOUT>
__global__ __launch_bounds__(256) void gemm_h(
    const __half* __restrict__ A, const __half* __restrict__ Bt,
    const float* __restrict__ bias, const float* __restrict__ res,
    float* __restrict__ Yf, __half* __restrict__ Yh, int M, int N, int K)
{
    extern __shared__ char gsm[];
    __half* As = reinterpret_cast<__half*>(gsm);          // 3 stages [128][GST]
    __half* Bs = As + 3*128*GST;                          // 3 stages [64][GST]

    const int tid  = threadIdx.x;
    const int lane = tid & 31;
    const int gid  = lane >> 2, tig = lane & 3;
    const int wid  = tid >> 5;
    const int wm   = wid >> 1, wn = wid & 1;
    const int bm   = blockIdx.y * 128, bn = blockIdx.x * 64;

    float acc[2][4][4];
    #pragma unroll
    for (int i = 0; i < 2; i++)
        #pragma unroll
        for (int j = 0; j < 4; j++)
            #pragma unroll
            for (int k = 0; k < 4; k++) acc[i][j][k] = 0.f;

    const int ar  = tid >> 2;           // A row 0..63 (+64)
    const int ac  = (tid & 3) * 8;      // A col chunk (16B)
    const int bn_ = tid >> 2;           // B n row 0..63
    const int bc  = (tid & 3) * 8;      // B k chunk

    auto stage = [&](int k0, int st){
        __half* Ad = As + st*128*GST;
        __half* Bd = Bs + st*64*GST;
        #pragma unroll
        for (int ir = 0; ir < 2; ir++){
            int r = ar + ir * 64;
            cpa16(&Ad[r * GST + ac], A + (size_t)(bm + r) * K + k0 + ac);
        }
        cpa16(&Bd[bn_ * GST + bc], Bt + (size_t)(bn + bn_) * K + k0 + bc);
        cpa_commit();
    };

    const int KIT = K >> 5;
    stage(0, 0);
    stage(32, 1);

    for (int it = 0; it < KIT; it++){
        if (it + 1 < KIT) cpa_wait<1>(); else cpa_wait<0>();
        __syncthreads();
        if (it + 2 < KIT) stage((it + 2) * 32, (it + 2) % 3);

        const __half* Ab = As + (it % 3)*128*GST;
        const __half* Bb = Bs + (it % 3)*64*GST;
        #pragma unroll
        for (int ks = 0; ks < 2; ks++){
            const int kc = ks * 16 + 4 * tig;      // interleaved k chunk
            uint32_t af[2][4];
            #pragma unroll
            for (int mt = 0; mt < 2; mt++){
                int r0 = wm*32 + mt*16 + gid;
                uint2 lo = lds64(&Ab[ r0      * GST + kc]);
                uint2 hi = lds64(&Ab[(r0 + 8) * GST + kc]);
                af[mt][0] = lo.x; af[mt][2] = lo.y;
                af[mt][1] = hi.x; af[mt][3] = hi.y;
            }
            #pragma unroll
            for (int nt = 0; nt < 4; nt++){
                uint2 bv = lds64(&Bb[(wn*32 + nt*8 + gid) * GST + kc]);
                #pragma unroll
                for (int mt = 0; mt < 2; mt++)
                    mma_f16(acc[mt][nt], af[mt], bv.x, bv.y);
            }
        }
    }

    #pragma unroll
    for (int mt = 0; mt < 2; mt++){
        #pragma unroll
        for (int nt = 0; nt < 4; nt++){
            int col = bn + wn * 32 + nt * 8 + 2 * tig;
            float b0 = bias[col], b1 = bias[col + 1];
            int r0 = bm + wm * 32 + mt * 16 + gid;
            #pragma unroll
            for (int hf = 0; hf < 2; hf++){
                int row = r0 + hf * 8;
                float v0 = acc[mt][nt][hf*2+0] + b0;
                float v1 = acc[mt][nt][hf*2+1] + b1;
                if (res){
                    v0 += res[(size_t)row * N + col];
                    v1 += res[(size_t)row * N + col + 1];
                }
                if (RELU){ v0 = fmaxf(v0, 0.f); v1 = fmaxf(v1, 0.f); }
                if (HOUT){
                    __half2 hv = __floats2half2_rn(v0, v1);
                    *reinterpret_cast<__half2*>(Yh + (size_t)row * N + col) = hv;
                } else {
                    *reinterpret_cast<float2*>(Yf + (size_t)row * N + col) = make_float2(v0, v1);
                }
            }
        }
    }
}

// ---------------- flash attention: 32 q-rows per warp, 256 q per CTA -----------
// 8 warps; warp tile 32q x 64keys; every K/V fragment feeds 2 mmas.
// S-phase uses LDS.64 k-interleave (Q regs + K smem). PV keeps LDS.32 pairs.
#define QST  80
#define KST2 80
#define VST  72
#define VTST 136
#define NT_TILES (Sv/128)
#define QROWS 256
#define ATTN_SMEM_BYTES ((QROWS*QST + 2*128*KST2 + 2*128*VST + 64*VTST)*2 + 2*128*4)

__global__ __launch_bounds__(256, 1) void attn_h(
    const __half* __restrict__ QKV, const float* __restrict__ negm,
    __half* __restrict__ O)
{
    extern __shared__ char smem_raw[];
    __half* sQ  = reinterpret_cast<__half*>(smem_raw);
    __half* sK0 = sQ  + QROWS*QST;
    __half* sK1 = sK0 + 128*KST2;
    __half* sV0 = sK1 + 128*KST2;
    __half* sV1 = sV0 + 128*VST;
    __half* sVT = sV1 + 128*VST;
    float* sMask0 = reinterpret_cast<float*>(sVT + 64*VTST);
    float* sMask1 = sMask0 + 128;

    const int tid = threadIdx.x, lane = tid & 31, wid = tid >> 5;
    const int gid = lane >> 2, tig = lane & 3;
    const int m0  = wid * 32;
    const int b   = blockIdx.y >> 2, h = blockIdx.y & 3;
    const int q0  = blockIdx.x * QROWS;
    const __half* Qb = QKV + (size_t)b*Sv*NQKV + (size_t)h*DEP;
    const __half* Kb = Qb + Dv;
    const __half* Vb = Qb + 2*Dv;
    const float*  Mb = negm + (size_t)b*Sv;

    const int sr  = tid >> 2;            // staging row 0..63
    const int sc  = (tid & 3) * 16;      // staging col (two 16B chunks)

    auto stageKVM = [&](int kt, __half* dK, __half* dV, float* dM){
        const int kbase = kt * 128;
        #pragma unroll
        for (int ir = 0; ir < 2; ir++){
            int row = sr + ir * 64;
            const __half* ks_ = Kb + (size_t)(kbase + row) * NQKV + sc;
            cpa16(&dK[row*KST2 + sc    ], ks_);
            cpa16(&dK[row*KST2 + sc + 8], ks_ + 8);
            const __half* vs_ = Vb + (size_t)(kbase + row) * NQKV + sc;
            cpa16(&dV[row*VST + sc    ], vs_);
            cpa16(&dV[row*VST + sc + 8], vs_ + 8);
        }
        if (tid < 32) cpa16(&dM[tid*4], Mb + kbase + tid*4);
    };

    // prologue: Q (256 rows) + tile0
    {
        #pragma unroll
        for (int ir = 0; ir < 4; ir++){
            int row = sr + ir * 64;
            const __half* src = Qb + (size_t)(q0 + row) * NQKV + sc;
            cpa16(&sQ[row*QST + sc    ], src);
            cpa16(&sQ[row*QST + sc + 8], src + 8);
        }
        stageKVM(0, sK0, sV0, sMask0);
        cpa_commit();
    }
    cpa_wait<0>();
    __syncthreads();

    // Q fragments in registers, k-interleaved layout (LDS.64)
    uint32_t qf[2][4][4];
    #pragma unroll
    for (int mt = 0; mt < 2; mt++){
        #pragma unroll
        for (int kd = 0; kd < 4; kd++){
            int r0 = m0 + mt*16 + gid;
            uint2 lo = lds64(&sQ[ r0      * QST + kd*16 + 4*tig]);
            uint2 hi = lds64(&sQ[(r0 + 8) * QST + kd*16 + 4*tig]);
            qf[mt][kd][0] = lo.x; qf[mt][kd][2] = lo.y;
            qf[mt][kd][1] = hi.x; qf[mt][kd][3] = hi.y;
        }
    }

    float o[2][8][4];
    #pragma unroll
    for (int mt = 0; mt < 2; mt++)
        #pragma unroll
        for (int i = 0; i < 8; i++){
            o[mt][i][0]=o[mt][i][1]=o[mt][i][2]=o[mt][i][3]=0.f;
        }
    float mrow[2][2] = {{-1e30f,-1e30f},{-1e30f,-1e30f}};
    float lrow[2][2] = {{0.f,0.f},{0.f,0.f}};

    const int vkp = tid & 63;            // V-transpose key pair
    const int vdb = (tid >> 6) * 8;      // V-transpose d base

    for (int kt = 0; kt < NT_TILES; kt++){
        const int buf = kt & 1;
        __half* cK = buf ? sK1 : sK0;
        __half* cV = buf ? sV1 : sV0;
        float*  cM = buf ? sMask1 : sMask0;
        const bool nxt = (kt + 1 < NT_TILES);
        if (nxt){
            stageKVM(kt + 1, buf ? sK0 : sK1, buf ? sV0 : sV1,
                     buf ? sMask0 : sMask1);
            cpa_commit();
        }

        // transpose V: cV[key][d] -> sVT[d][key]
        #pragma unroll
        for (int it = 0; it < 2; it++){
            int d0 = vdb + it * 32;
            uint4 va = *reinterpret_cast<const uint4*>(&cV[(2*vkp    )*VST + d0]);
            uint4 vb = *reinterpret_cast<const uint4*>(&cV[(2*vkp + 1)*VST + d0]);
            const __half* ha = reinterpret_cast<const __half*>(&va);
            const __half* hb = reinterpret_cast<const __half*>(&vb);
            #pragma unroll
            for (int j = 0; j < 8; j++){
                __half2 pr = __halves2half2(ha[j], hb[j]);
                *reinterpret_cast<uint32_t*>(&sVT[(d0+j)*VTST + 2*vkp]) =
                    *reinterpret_cast<uint32_t*>(&pr);
            }
        }

        #pragma unroll
        for (int hh2 = 0; hh2 < 2; hh2++){
            const int kh0 = hh2 * 64;
            // ---- S = Q @ K^T over 64 keys, both m-tiles share B-fragments ----
            float p[2][8][4];
            #pragma unroll
            for (int mt = 0; mt < 2; mt++)
                #pragma unroll
                for (int nt = 0; nt < 8; nt++){
                    p[mt][nt][0]=p[mt][nt][1]=p[mt][nt][2]=p[mt][nt][3]=0.f;
                }
            #pragma unroll
            for (int kd = 0; kd < 4; kd++){
                #pragma unroll
                for (int nt = 0; nt < 8; nt++){
                    uint2 bv = lds64(&cK[(kh0 + nt*8 + gid)*KST2 + kd*16 + 4*tig]);
                    mma_f16(p[0][nt], qf[0][kd], bv.x, bv.y);
                    mma_f16(p[1][nt], qf[1][kd], bv.x, bv.y);
                }
            }
            if (hh2 == 0) __syncthreads();   // sVT visible before PV reads

            // ---- online softmax per m-tile ----
            #pragma unroll
            for (int mt = 0; mt < 2; mt++){
                float rmax[2] = {-1e30f, -1e30f};
                #pragma unroll
                for (int nt = 0; nt < 8; nt++){
                    #pragma unroll
                    for (int j = 0; j < 4; j++){
                        int key = kh0 + nt*8 + 2*tig + (j & 1);
                        float s = fmaf(p[mt][nt][j], 0.125f, cM[key]);
                        p[mt][nt][j] = s;
                        rmax[j>>1] = fmaxf(rmax[j>>1], s);
                    }
                }
                #pragma unroll
                for (int hh = 0; hh < 2; hh++){
                    rmax[hh] = fmaxf(rmax[hh], __shfl_xor_sync(0xffffffffu, rmax[hh], 1));
                    rmax[hh] = fmaxf(rmax[hh], __shfl_xor_sync(0xffffffffu, rmax[hh], 2));
                }
                float mnew[2], alpha[2], rsum[2];
                #pragma unroll
                for (int hh = 0; hh < 2; hh++){
                    mnew[hh]  = fmaxf(mrow[mt][hh], rmax[hh]);
                    alpha[hh] = __expf(mrow[mt][hh] - mnew[hh]);
                    rsum[hh]  = 0.f;
                }
                #pragma unroll
                for (int nt = 0; nt < 8; nt++){
                    #pragma unroll
                    for (int j = 0; j < 4; j++){
                        float e = __expf(p[mt][nt][j] - mnew[j>>1]);
                        p[mt][nt][j] = e;
                        rsum[j>>1] += e;
                    }
                }
                #pragma unroll
                for (int hh = 0; hh < 2; hh++){
                    rsum[hh] += __shfl_xor_sync(0xffffffffu, rsum[hh], 1);
                    rsum[hh] += __shfl_xor_sync(0xffffffffu, rsum[hh], 2);
                    lrow[mt][hh] = lrow[mt][hh] * alpha[hh] + rsum[hh];
                    mrow[mt][hh] = mnew[hh];
                }
                #pragma unroll
                for (int nt = 0; nt < 8; nt++){
                    o[mt][nt][0] *= alpha[0]; o[mt][nt][1] *= alpha[0];
                    o[mt][nt][2] *= alpha[1]; o[mt][nt][3] *= alpha[1];
                }
            }

            // ---- O += P @ V, both m-tiles share V fragments ----
            #pragma unroll
            for (int ks = 0; ks < 4; ks++){
                uint32_t ap[2][4];
                #pragma unroll
                for (int mt = 0; mt < 2; mt++){
                    ap[mt][0] = pack2(p[mt][2*ks  ][0], p[mt][2*ks  ][1]);
                    ap[mt][1] = pack2(p[mt][2*ks  ][2], p[mt][2*ks  ][3]);
                    ap[mt][2] = pack2(p[mt][2*ks+1][0], p[mt][2*ks+1][1]);
                    ap[mt][3] = pack2(p[mt][2*ks+1][2], p[mt][2*ks+1][3]);
                }
                #pragma unroll
                for (int nt = 0; nt < 8; nt++){
                    const __half* vbp = &sVT[(nt*8 + gid)*VTST + kh0 + ks*16 + 2*tig];
                    uint32_t b0 = lds32(vbp);
                    uint32_t b1 = lds32(vbp + 8);
                    mma_f16(o[0][nt], ap[0], b0, b1);
                    mma_f16(o[1][nt], ap[1], b0, b1);
                }
            }
        }
        if (nxt) cpa_wait<0>();
        __syncthreads();
    }

    #pragma unroll
    for (int mt = 0; mt < 2; mt++){
        float inv0 = 1.f / lrow[mt][0], inv1 = 1.f / lrow[mt][1];
        #pragma unroll
        for (int nt = 0; nt < 8; nt++){
            int col  = h * DEP + nt * 8 + 2 * tig;
            int row0 = q0 + m0 + mt*16 + gid;
            __half2 h0 = __floats2half2_rn(o[mt][nt][0]*inv0, o[mt][nt][1]*inv0);
            __half2 h1 = __floats2half2_rn(o[mt][nt][2]*inv1, o[mt][nt][3]*inv1);
            *reinterpret_cast<__half2*>(O + (size_t)(b*Sv + row0    )*Dv + col) = h0;
            *reinterpret_cast<__half2*>(O + (size_t)(b*Sv + row0 + 8)*Dv + col) = h1;
        }
    }
}

// ---------------- LayerNorm: warp per row --------------------------------------
__global__ __launch_bounds__(256) void ln_kernel(
    const float* __restrict__ in, float* __restrict__ out, __half* __restrict__ outh,
    const float* __restrict__ g, const float* __restrict__ bt,
    int N, float eps)
{
    const int lane = threadIdx.x & 31;
    const int row  = blockIdx.x * 8 + (threadIdx.x >> 5);
    const int nch  = N >> 7;
    const float* x = in + (size_t)row * N;

    float4 v[8];
    float s = 0.f;
    for (int j = 0; j < nch; j++){
        v[j] = *reinterpret_cast<const float4*>(x + j*128 + lane*4);
        s += v[j].x + v[j].y + v[j].z + v[j].w;
    }
    #pragma unroll
    for (int o = 16; o; o >>= 1) s += __shfl_xor_sync(0xffffffffu, s, o);
    float mu = s / N;
    float var = 0.f;
    for (int j = 0; j < nch; j++){
        float dx = v[j].x-mu, dy = v[j].y-mu, dz = v[j].z-mu, dw = v[j].w-mu;
        var += dx*dx + dy*dy + dz*dz + dw*dw;
    }
    #pragma unroll
    for (int o = 16; o; o >>= 1) var += __shfl_xor_sync(0xffffffffu, var, o);
    float rstd = rsqrtf(var / N + eps);

    for (int j = 0; j < nch; j++){
        int c = j*128 + lane*4;
        float4 gg = *reinterpret_cast<const float4*>(g  + c);
        float4 bb = *reinterpret_cast<const float4*>(bt + c);
        float y0 = (v[j].x - mu) * rstd * gg.x + bb.x;
        float y1 = (v[j].y - mu) * rstd * gg.y + bb.y;
        float y2 = (v[j].z - mu) * rstd * gg.z + bb.z;
        float y3 = (v[j].w - mu) * rstd * gg.w + bb.w;
        if (out)
            *reinterpret_cast<float4*>(out + (size_t)row * N + c) =
                make_float4(y0, y1, y2, y3);
        if (outh){
            uint2 u;
            u.x = pack2(y0, y1);
            u.y = pack2(y2, y3);
            *reinterpret_cast<uint2*>(outh + (size_t)row * N + c) = u;
        }
    }
}

// ---------------- launch --------------------------------------------------------
extern "C" void kernel_launch(void* const* d_in, const int* in_sizes, int n_in,
                              void* d_out, int out_size)
{
    (void)in_sizes; (void)n_in; (void)out_size;
    const float* x    = (const float*)d_in[0];
    const float* mask = (const float*)d_in[1];
    const float* wq   = (const float*)d_in[2];
    const float* bq   = (const float*)d_in[3];
    const float* wk   = (const float*)d_in[4];
    const float* bk   = (const float*)d_in[5];
    const float* wv   = (const float*)d_in[6];
    const float* bv   = (const float*)d_in[7];
    const float* wo   = (const float*)d_in[8];
    const float* bo   = (const float*)d_in[9];
    const float* w1   = (const float*)d_in[10];
    const float* b1   = (const float*)d_in[11];
    const float* lnffg= (const float*)d_in[12];
    const float* lnffb= (const float*)d_in[13];
    const float* w2   = (const float*)d_in[14];
    const float* b2   = (const float*)d_in[15];
    const float* ln1g = (const float*)d_in[16];
    const float* ln1b = (const float*)d_in[17];
    const float* ln2g = (const float*)d_in[18];
    const float* ln2b = (const float*)d_in[19];
    float* out = (float*)d_out;

    float  *X1, *Hb, *negm, *bqkv;
    __half *xh, *QKVh, *ctxh, *x1h, *hh;
    __half *wqkvT, *woT, *w1T, *w2T;
    cudaGetSymbolAddress((void**)&X1,    g_X1);
    cudaGetSymbolAddress((void**)&Hb,    g_H);
    cudaGetSymbolAddress((void**)&negm,  g_negm);
    cudaGetSymbolAddress((void**)&bqkv,  g_bqkv);
    cudaGetSymbolAddress((void**)&xh,    g_xh);
    cudaGetSymbolAddress((void**)&QKVh,  g_QKVh);
    cudaGetSymbolAddress((void**)&ctxh,  g_ctxh);
    cudaGetSymbolAddress((void**)&x1h,   g_x1h);
    cudaGetSymbolAddress((void**)&hh,    g_hh);
    cudaGetSymbolAddress((void**)&wqkvT, g_wqkvT);
    cudaGetSymbolAddress((void**)&woT,   g_woT);
    cudaGetSymbolAddress((void**)&w1T,   g_w1T);
    cudaGetSymbolAddress((void**)&w2T,   g_w2T);

    cudaFuncSetAttribute(attn_h, cudaFuncAttributeMaxDynamicSharedMemorySize,
                         ATTN_SMEM_BYTES);
    cudaFuncSetAttribute(gemm_h<false,true>,  cudaFuncAttributeMaxDynamicSharedMemorySize, GEMM_SMEM_BYTES);
    cudaFuncSetAttribute(gemm_h<false,false>, cudaFuncAttributeMaxDynamicSharedMemorySize, GEMM_SMEM_BYTES);
    cudaFuncSetAttribute(gemm_h<true,false>,  cudaFuncAttributeMaxDynamicSharedMemorySize, GEMM_SMEM_BYTES);

    const dim3 blk(256);
    const dim3 gQKV(NQKV/64, MTOK/128);
    const dim3 gP(Dv/64,    MTOK/128);
    const dim3 gF(DFFv/64,  MTOK/128);

    // prep
    cvt_kernel<<<(MTOK*Dv/4 + 255)/256, blk>>>(x, xh, MTOK*Dv/4);
    prep_kernel<<<(NQKV + Bv*Sv + 255)/256, blk>>>(bq, bk, bv, mask, bqkv, negm);
    transp_all<<<768, dim3(32,8)>>>(wq, wk, wv, wo, w1, w2,
                                    wqkvT, woT, w1T, w2T);
    // fused QKV projection
    gemm_h<false,true><<<gQKV, blk, GEMM_SMEM_BYTES>>>(xh, wqkvT, bqkv, nullptr,
                                                       nullptr, QKVh, MTOK, NQKV, Dv);
    // attention
    attn_h<<<dim3(Sv/QROWS, Bv*Hv), blk, ATTN_SMEM_BYTES>>>(QKVh, negm, ctxh);
    // out-proj + residual, LN1
    gemm_h<false,false><<<gP, blk, GEMM_SMEM_BYTES>>>(ctxh, woT, bo, x, X1, nullptr,
                                                      MTOK, Dv, Dv);
    ln_kernel<<<MTOK/8, blk>>>(X1, X1, x1h, ln1g, ln1b, Dv, 1e-3f);
    // FFN1 + relu, LN_ff
    gemm_h<true,false><<<gF, blk, GEMM_SMEM_BYTES>>>(x1h, w1T, b1, nullptr, Hb, nullptr,
                                                     MTOK, DFFv, Dv);
    ln_kernel<<<MTOK/8, blk>>>(Hb, nullptr, hh, lnffg, lnffb, DFFv, 1e-6f);
    // FFN2 + residual, LN2
    gemm_h<false,false><<<gP, blk, GEMM_SMEM_BYTES>>>(hh, w2T, b2, X1, out, nullptr,
                                                      MTOK, Dv, DFFv);
    ln_kernel<<<MTOK/8, blk>>>(out, out, nullptr, ln2g, ln2b, Dv, 1e-3f);
}